// round 2
// baseline (speedup 1.0000x reference)
#include <cuda_runtime.h>
#include <cuda_fp16.h>
#include <cstdint>

#define NN 100000
#define EE 1000000
#define FEAT 128
#define NLAB 2048
#define MPAD 100096            // 391 * 256
#define KEXT 384               // hi | hi | lo  fp16 split
#define NBLK_SCAN 98           // ceil(100000/1024)

// GEMM tiling
#define TM 256                 // rows per CTA (A resident in smem)
#define KCH 64                 // K elements per chunk (128 bytes fp16)
#define NCHUNK 6               // 384 / 64
#define A_CH_BYTES (TM * 128)        // 32768 per K-chunk
#define B_OFFSET (NCHUNK * A_CH_BYTES) // 196608
#define B_CH_BYTES (128 * 128)       // 16384 (128 n-rows x 64 k fp16)
#define SMEM_TOTAL (B_OFFSET + 2 * B_CH_BYTES)  // 229376

// ======================= device scratch =====================================
static __device__ __align__(16) __half g_Asplit[(size_t)MPAD * KEXT]; // 76.9 MB
static __device__ __align__(16) __half g_Bsplit[(size_t)NLAB * KEXT]; //  1.6 MB
static __device__ __align__(16) float g_H[(size_t)MPAD * FEAT];       // 51.2 MB
static __device__ __align__(16) float g_X[(size_t)MPAD * FEAT];       // 51.2 MB
static __device__ float g_deg[NN];
static __device__ float g_dinv[NN];
static __device__ int   g_cnt[NN];
static __device__ int   g_colptr[NN];
static __device__ int   g_cursor[NN];
static __device__ int   g_bsum[128];
static __device__ int   g_bofs[128];
static __device__ int   g_esrc[EE];
static __device__ float g_eww[EE];

// ======================= helpers ============================================
__device__ __forceinline__ uint32_t smem_u32(const void* p) {
    uint32_t a;
    asm("{ .reg .u64 t; cvta.to.shared.u64 t, %1; cvt.u32.u64 %0, t; }" : "=r"(a) : "l"(p));
    return a;
}
#define SWZ128(x) ((x) ^ (((x) >> 3) & 0x70))

__device__ __forceinline__ void cpa16(uint32_t s, const void* g) {
    asm volatile("cp.async.cg.shared.global [%0], [%1], 16;"
                 :: "r"(s), "l"(__cvta_generic_to_global(g)) : "memory");
}
__device__ __forceinline__ void cpa_commit() {
    asm volatile("cp.async.commit_group;" ::: "memory");
}
__device__ __forceinline__ void cpa_wait1() {
    asm volatile("cp.async.wait_group 1;" ::: "memory");
}
__device__ __forceinline__ void ldmA4(uint32_t* r, uint32_t addr) {
    asm volatile("ldmatrix.sync.aligned.m8n8.x4.shared.b16 {%0,%1,%2,%3}, [%4];"
                 : "=r"(r[0]), "=r"(r[1]), "=r"(r[2]), "=r"(r[3]) : "r"(addr));
}
__device__ __forceinline__ void mma16816(float* d, const uint32_t* a, uint32_t b0, uint32_t b1) {
    asm volatile(
        "mma.sync.aligned.m16n8k16.row.col.f32.f16.f16.f32 "
        "{%0,%1,%2,%3}, {%4,%5,%6,%7}, {%8,%9}, {%0,%1,%2,%3};"
        : "+f"(d[0]), "+f"(d[1]), "+f"(d[2]), "+f"(d[3])
        : "r"(a[0]), "r"(a[1]), "r"(a[2]), "r"(a[3]), "r"(b0), "r"(b1));
}

// ======================= graph preprocessing ================================
__global__ void k_init() {
    int i = blockIdx.x * blockDim.x + threadIdx.x;
    if (i < NN) { g_deg[i] = 1.0f; g_cnt[i] = 0; }
}
__global__ void k_hist(const int* __restrict__ row, const int* __restrict__ col,
                       const float* __restrict__ ew) {
    int e = blockIdx.x * blockDim.x + threadIdx.x;
    if (e < EE) {
        int c = col[e];
        atomicAdd(&g_deg[c], ew[e]);
        atomicAdd(&g_cnt[c], 1);
    }
}
__global__ void k_dinv() {
    int i = blockIdx.x * blockDim.x + threadIdx.x;
    if (i < NN) g_dinv[i] = rsqrtf(g_deg[i]);
}
__global__ void k_scanA() {
    __shared__ int s[1024];
    int t = threadIdx.x;
    int i = blockIdx.x * 1024 + t;
    int v = (i < NN) ? g_cnt[i] : 0;
    s[t] = v;
    __syncthreads();
    for (int off = 1; off < 1024; off <<= 1) {
        int add = (t >= off) ? s[t - off] : 0;
        __syncthreads();
        s[t] += add;
        __syncthreads();
    }
    if (i < NN) g_colptr[i] = s[t] - v;
    if (t == 1023) g_bsum[blockIdx.x] = s[1023];
}
__global__ void k_scanB() {
    int acc = 0;
    for (int b = 0; b < NBLK_SCAN; b++) { g_bofs[b] = acc; acc += g_bsum[b]; }
}
__global__ void k_scanC() {
    int i = blockIdx.x * 1024 + threadIdx.x;
    if (i < NN) {
        int ex = g_colptr[i] + g_bofs[blockIdx.x];
        g_colptr[i] = ex;
        g_cursor[i] = ex;
    }
}
__global__ void k_fill(const int* __restrict__ row, const int* __restrict__ col,
                       const float* __restrict__ ew) {
    int e = blockIdx.x * blockDim.x + threadIdx.x;
    if (e < EE) {
        int c = col[e], r = row[e];
        int pos = atomicAdd(&g_cursor[c], 1);
        g_esrc[pos] = r;
        g_eww[pos] = g_dinv[r] * ew[e] * g_dinv[c];
    }
}

// ======================= hi/lo fp16 split ===================================
// A' = [hi | hi | lo], B' = [hi | lo | hi] -> ahi*bhi + ahi*blo + alo*bhi
__global__ void k_splitA(const float* __restrict__ ext, const int* __restrict__ idx,
                         int use_internal) {
    const size_t total = (size_t)MPAD * FEAT;
    for (size_t i = (size_t)blockIdx.x * blockDim.x + threadIdx.x; i < total;
         i += (size_t)gridDim.x * blockDim.x) {
        int m = (int)(i >> 7), k = (int)(i & 127);
        float v = 0.0f;
        if (m < NN) {
            if (use_internal) v = g_X[(size_t)m * FEAT + k];
            else {
                int r = idx[m];
                v = ext[(size_t)r * FEAT + k];
            }
        }
        __half hi = __float2half(v);
        __half lo = __float2half(v - __half2float(hi));
        size_t base = (size_t)m * KEXT;
        g_Asplit[base + k] = hi;
        g_Asplit[base + 128 + k] = hi;
        g_Asplit[base + 256 + k] = lo;
    }
}
__global__ void k_splitB(const float* __restrict__ W, int ncols) {
    int total = ncols * FEAT;
    for (int i = blockIdx.x * blockDim.x + threadIdx.x; i < total;
         i += gridDim.x * blockDim.x) {
        int nr = i >> 7, k = i & 127;
        float v = W[(size_t)k * ncols + nr];
        __half hi = __float2half(v);
        __half lo = __float2half(v - __half2float(hi));
        size_t base = (size_t)nr * KEXT;
        g_Bsplit[base + k] = hi;
        g_Bsplit[base + 128 + k] = lo;
        g_Bsplit[base + 256 + k] = hi;
    }
}

// ======================= mma.sync GEMM ======================================
// C[m0:m0+256, :] = Asplit[m0:m0+256, 384] @ Bsplit[:, 384]^T
// 512 threads = 16 warps (4m x 4n), warp tile 64x32, full A tile in SMEM,
// B streamed in 64-K chunks double-buffered with cp.async. n-loop inside CTA.
__global__ void __launch_bounds__(512, 1)
gemm_kernel(float* __restrict__ Cext, int dst_sel, int ldC, int nIters, int Mreal,
            const float* __restrict__ bias) {
    extern __shared__ char smem[];
    uint32_t sb = smem_u32(smem);
    int tid = threadIdx.x, lid = tid & 31, wid = tid >> 5;
    int warp_m = wid >> 2, warp_n = wid & 3;
    int m0 = blockIdx.x * TM;

    float* C = dst_sel ? Cext : g_H;
    const __half* Ag = g_Asplit + (size_t)m0 * KEXT;

    // issue all A chunks (192 KB) + B(iter 0, chunk 0) as group 0
    #pragma unroll
    for (int c = 0; c < NCHUNK; c++) {
        for (int i = tid; i < TM * 8; i += 512) {
            int r = i >> 3, s = i & 7;
            cpa16(sb + c * A_CH_BYTES + SWZ128(r * 128 + s * 16),
                  Ag + (size_t)r * KEXT + c * KCH + s * 8);
        }
    }
    for (int i = tid; i < 128 * 8; i += 512) {
        int r = i >> 3, s = i & 7;
        cpa16(sb + B_OFFSET + SWZ128(r * 128 + s * 16),
              g_Bsplit + (size_t)r * KEXT + s * 8);
    }
    cpa_commit();

    // precomputed ldmatrix lane addressing
    const int a_row = warp_m * 64 + (lid & 7) + ((lid >> 3) & 1) * 8;  // + mi*16
    const int a_ks  = (lid >> 4) * 8;                                   // + ks*16
    const int b_row = warp_n * 32 + (lid & 7) + ((lid >> 4) & 1) * 8;   // + bi*16
    const int b_ks  = ((lid >> 3) & 1) * 8;                             // + ks*16

    for (int it = 0; it < nIters; it++) {
        float acc[4][4][4];
        #pragma unroll
        for (int mi = 0; mi < 4; mi++)
            #pragma unroll
            for (int nj = 0; nj < 4; nj++)
                #pragma unroll
                for (int q = 0; q < 4; q++) acc[mi][nj][q] = 0.0f;

        for (int c = 0; c < NCHUNK; c++) {
            // prefetch next B chunk into the other buffer
            int buf = c & 1;               // (it*6 + c) & 1 == c & 1 since 6 even
            int nc = c + 1, nit = it;
            if (nc == NCHUNK) { nc = 0; nit = it + 1; }
            if (nit < nIters) {
                const __half* Bg = g_Bsplit + (size_t)(nit * 128) * KEXT + nc * KCH;
                uint32_t bb = sb + B_OFFSET + (buf ^ 1) * B_CH_BYTES;
                for (int i = tid; i < 128 * 8; i += 512) {
                    int r = i >> 3, s = i & 7;
                    cpa16(bb + SWZ128(r * 128 + s * 16), Bg + (size_t)r * KEXT + s * 8);
                }
            }
            cpa_commit();
            cpa_wait1();
            __syncthreads();

            uint32_t Ab = sb + c * A_CH_BYTES;
            uint32_t Bb = sb + B_OFFSET + buf * B_CH_BYTES;
            #pragma unroll
            for (int ks = 0; ks < 4; ks++) {
                uint32_t a[4][4], b[2][4];
                #pragma unroll
                for (int mi = 0; mi < 4; mi++)
                    ldmA4(a[mi], Ab + SWZ128((a_row + mi * 16) * 128 + (a_ks + ks * 16) * 2));
                #pragma unroll
                for (int bi = 0; bi < 2; bi++)
                    ldmA4(b[bi], Bb + SWZ128((b_row + bi * 16) * 128 + (b_ks + ks * 16) * 2));
                #pragma unroll
                for (int mi = 0; mi < 4; mi++)
                    #pragma unroll
                    for (int nj = 0; nj < 4; nj++)
                        mma16816(acc[mi][nj], a[mi], b[nj >> 1][(nj & 1) * 2],
                                 b[nj >> 1][(nj & 1) * 2 + 1]);
            }
            __syncthreads();
        }

        // epilogue for this n-tile
        int n0 = it * 128;
        #pragma unroll
        for (int mi = 0; mi < 4; mi++) {
            int r0 = m0 + warp_m * 64 + mi * 16 + (lid >> 2);
            #pragma unroll
            for (int nj = 0; nj < 4; nj++) {
                int col = n0 + warp_n * 32 + nj * 8 + ((lid & 3) << 1);
                float bx = bias ? bias[col] : 0.0f;
                float by = bias ? bias[col + 1] : 0.0f;
                if (r0 < Mreal) {
                    float2 o = {acc[mi][nj][0] + bx, acc[mi][nj][1] + by};
                    *(float2*)(C + (size_t)r0 * ldC + col) = o;
                }
                if (r0 + 8 < Mreal) {
                    float2 o = {acc[mi][nj][2] + bx, acc[mi][nj][3] + by};
                    *(float2*)(C + (size_t)(r0 + 8) * ldC + col) = o;
                }
            }
        }
    }
}

// ======================= SpMM (CSC gather, warp per node) ===================
__global__ void k_spmm(const float* __restrict__ bias) {
    int gw = (blockIdx.x * blockDim.x + threadIdx.x) >> 5;
    int lane = threadIdx.x & 31;
    if (gw >= NN) return;
    const float4* H4 = (const float4*)g_H;
    float di = g_dinv[gw];
    float s = di * di;
    float4 acc = H4[(size_t)gw * 32 + lane];
    acc.x *= s; acc.y *= s; acc.z *= s; acc.w *= s;
    int start = g_colptr[gw];
    int len = g_cnt[gw];
    for (int j = 0; j < len; j++) {
        int e = start + j;
        int src = g_esrc[e];
        float w = g_eww[e];
        float4 v = H4[(size_t)src * 32 + lane];
        acc.x += w * v.x; acc.y += w * v.y; acc.z += w * v.z; acc.w += w * v.w;
    }
    float4 b4 = ((const float4*)bias)[lane];
    acc.x = fmaxf(acc.x + b4.x, 0.0f);
    acc.y = fmaxf(acc.y + b4.y, 0.0f);
    acc.z = fmaxf(acc.z + b4.z, 0.0f);
    acc.w = fmaxf(acc.w + b4.w, 0.0f);
    ((float4*)g_X)[(size_t)gw * 32 + lane] = acc;
}

// ======================= launch =============================================
extern "C" void kernel_launch(void* const* d_in, const int* in_sizes, int n_in,
                              void* d_out, int out_size) {
    const int*   node_idx = (const int*)d_in[0];
    const int*   ei       = (const int*)d_in[1];     // [2, E]
    const float* ew       = (const float*)d_in[2];
    const float* emb      = (const float*)d_in[3];
    const float* W1       = (const float*)d_in[4];
    const float* b1       = (const float*)d_in[5];
    const float* W2       = (const float*)d_in[6];
    const float* b2       = (const float*)d_in[7];
    const float* Wout     = (const float*)d_in[8];
    const float* bout     = (const float*)d_in[9];
    float* out = (float*)d_out;
    const int* row = ei;
    const int* col = ei + EE;

    cudaFuncSetAttribute(gemm_kernel, cudaFuncAttributeMaxDynamicSharedMemorySize,
                         SMEM_TOTAL);

    // graph preprocessing (CSC by destination + symmetric norm)
    k_init<<<(NN + 255) / 256, 256>>>();
    k_hist<<<(EE + 255) / 256, 256>>>(row, col, ew);
    k_dinv<<<(NN + 255) / 256, 256>>>();
    k_scanA<<<NBLK_SCAN, 1024>>>();
    k_scanB<<<1, 1>>>();
    k_scanC<<<NBLK_SCAN, 1024>>>();
    k_fill<<<(EE + 255) / 256, 256>>>(row, col, ew);

    const int gemm_grid = MPAD / TM;                 // 391
    const int spmm_grid = (NN + 7) / 8;

    // layer 1
    k_splitA<<<4096, 256>>>(emb, node_idx, 0);
    k_splitB<<<64, 256>>>(W1, FEAT);
    gemm_kernel<<<gemm_grid, 512, SMEM_TOTAL>>>(nullptr, 0, FEAT, 1, MPAD, nullptr);
    k_spmm<<<spmm_grid, 256>>>(b1);

    // layer 2
    k_splitA<<<4096, 256>>>(nullptr, node_idx, 1);
    k_splitB<<<64, 256>>>(W2, FEAT);
    gemm_kernel<<<gemm_grid, 512, SMEM_TOTAL>>>(nullptr, 0, FEAT, 1, MPAD, nullptr);
    k_spmm<<<spmm_grid, 256>>>(b2);

    // output layer
    k_splitA<<<4096, 256>>>(nullptr, node_idx, 1);
    k_splitB<<<1024, 256>>>(Wout, NLAB);
    gemm_kernel<<<gemm_grid, 512, SMEM_TOTAL>>>(out, 1, NLAB, NLAB / 128, NN, bout);
}

// round 3
// speedup vs baseline: 1.2548x; 1.2548x over previous
#include <cuda_runtime.h>
#include <cuda_fp16.h>
#include <cstdint>

#define NN 100000
#define EE 1000000
#define FEAT 128
#define NLAB 2048
#define MPAD 100096            // 391 * 256
#define KE3 384                // 3-term: A=[hi|hi|lo], B=[hi|lo|hi]
#define KE2 256                // 2-term: A=[hi|lo],    B=[hi|hi]
#define NBLK_SCAN 98

// GEMM tiling
#define TM 256
#define KCH 64
#define A_CH_BYTES (TM * 128)          // 32768
#define B_CH_BYTES (128 * 128)         // 16384

// ======================= device scratch =====================================
static __device__ __align__(16) __half g_Asplit[(size_t)MPAD * KE3]; // 76.9 MB
static __device__ __align__(16) __half g_Bsplit[(size_t)NLAB * KE3]; //  1.6 MB
static __device__ __align__(16) float g_H[(size_t)MPAD * FEAT];      // 51.2 MB
static __device__ float g_deg[NN];
static __device__ float g_dinv[NN];
static __device__ int   g_cnt[NN];
static __device__ int   g_colptr[NN];
static __device__ int   g_cursor[NN];
static __device__ int   g_bsum[128];
static __device__ int   g_bofs[128];
static __device__ int   g_esrc[EE];
static __device__ float g_eww[EE];

// ======================= helpers ============================================
__device__ __forceinline__ uint32_t smem_u32(const void* p) {
    uint32_t a;
    asm("{ .reg .u64 t; cvta.to.shared.u64 t, %1; cvt.u32.u64 %0, t; }" : "=r"(a) : "l"(p));
    return a;
}
#define SWZ128(x) ((x) ^ (((x) >> 3) & 0x70))

__device__ __forceinline__ void cpa16(uint32_t s, const void* g) {
    asm volatile("cp.async.cg.shared.global [%0], [%1], 16;"
                 :: "r"(s), "l"(__cvta_generic_to_global(g)) : "memory");
}
__device__ __forceinline__ void cpa_commit() {
    asm volatile("cp.async.commit_group;" ::: "memory");
}
__device__ __forceinline__ void cpa_wait1() {
    asm volatile("cp.async.wait_group 1;" ::: "memory");
}
__device__ __forceinline__ void ldmA4(uint32_t* r, uint32_t addr) {
    asm volatile("ldmatrix.sync.aligned.m8n8.x4.shared.b16 {%0,%1,%2,%3}, [%4];"
                 : "=r"(r[0]), "=r"(r[1]), "=r"(r[2]), "=r"(r[3]) : "r"(addr));
}
__device__ __forceinline__ void mma16816(float* d, const uint32_t* a, uint32_t b0, uint32_t b1) {
    asm volatile(
        "mma.sync.aligned.m16n8k16.row.col.f32.f16.f16.f32 "
        "{%0,%1,%2,%3}, {%4,%5,%6,%7}, {%8,%9}, {%0,%1,%2,%3};"
        : "+f"(d[0]), "+f"(d[1]), "+f"(d[2]), "+f"(d[3])
        : "r"(a[0]), "r"(a[1]), "r"(a[2]), "r"(a[3]), "r"(b0), "r"(b1));
}

// ======================= graph preprocessing ================================
__global__ void k_init() {
    int i = blockIdx.x * blockDim.x + threadIdx.x;
    if (i < NN) { g_deg[i] = 1.0f; g_cnt[i] = 0; }
}
__global__ void k_hist(const int* __restrict__ row, const int* __restrict__ col,
                       const float* __restrict__ ew) {
    int e = blockIdx.x * blockDim.x + threadIdx.x;
    if (e < EE) {
        int c = col[e];
        atomicAdd(&g_deg[c], ew[e]);
        atomicAdd(&g_cnt[c], 1);
    }
}
__global__ void k_dinv() {
    int i = blockIdx.x * blockDim.x + threadIdx.x;
    if (i < NN) g_dinv[i] = rsqrtf(g_deg[i]);
}
__global__ void k_scanA() {
    __shared__ int s[1024];
    int t = threadIdx.x;
    int i = blockIdx.x * 1024 + t;
    int v = (i < NN) ? g_cnt[i] : 0;
    s[t] = v;
    __syncthreads();
    for (int off = 1; off < 1024; off <<= 1) {
        int add = (t >= off) ? s[t - off] : 0;
        __syncthreads();
        s[t] += add;
        __syncthreads();
    }
    if (i < NN) g_colptr[i] = s[t] - v;
    if (t == 1023) g_bsum[blockIdx.x] = s[1023];
}
__global__ void k_scanB() {
    int acc = 0;
    for (int b = 0; b < NBLK_SCAN; b++) { g_bofs[b] = acc; acc += g_bsum[b]; }
}
__global__ void k_scanC() {
    int i = blockIdx.x * 1024 + threadIdx.x;
    if (i < NN) {
        int ex = g_colptr[i] + g_bofs[blockIdx.x];
        g_colptr[i] = ex;
        g_cursor[i] = ex;
    }
}
__global__ void k_fill(const int* __restrict__ row, const int* __restrict__ col,
                       const float* __restrict__ ew) {
    int e = blockIdx.x * blockDim.x + threadIdx.x;
    if (e < EE) {
        int c = col[e], r = row[e];
        int pos = atomicAdd(&g_cursor[c], 1);
        g_esrc[pos] = r;
        g_eww[pos] = g_dinv[r] * ew[e] * g_dinv[c];
    }
}

// ======================= splits =============================================
// Layer-1 A: gather emb rows, 3-term [hi|hi|lo]
__global__ void k_splitA1(const float* __restrict__ emb, const int* __restrict__ idx) {
    const size_t total = (size_t)NN * FEAT;
    for (size_t i = (size_t)blockIdx.x * blockDim.x + threadIdx.x; i < total;
         i += (size_t)gridDim.x * blockDim.x) {
        int m = (int)(i >> 7), k = (int)(i & 127);
        float v = emb[(size_t)idx[m] * FEAT + k];
        __half hi = __float2half(v);
        __half lo = __float2half(v - __half2float(hi));
        size_t base = (size_t)m * KE3;
        g_Asplit[base + k] = hi;
        g_Asplit[base + 128 + k] = hi;
        g_Asplit[base + 256 + k] = lo;
    }
}
// B: mode3 -> [hi|lo|hi] with stride KE3; else [hi|hi] with stride KE2
__global__ void k_splitB(const float* __restrict__ W, int ncols, int mode3) {
    int total = ncols * FEAT;
    for (int i = blockIdx.x * blockDim.x + threadIdx.x; i < total;
         i += gridDim.x * blockDim.x) {
        int nr = i >> 7, k = i & 127;
        float v = W[(size_t)k * ncols + nr];
        __half hi = __float2half(v);
        __half lo = __float2half(v - __half2float(hi));
        if (mode3) {
            size_t base = (size_t)nr * KE3;
            g_Bsplit[base + k] = hi;
            g_Bsplit[base + 128 + k] = lo;
            g_Bsplit[base + 256 + k] = hi;
        } else {
            size_t base = (size_t)nr * KE2;
            g_Bsplit[base + k] = hi;
            g_Bsplit[base + 128 + k] = hi;
        }
    }
}

// ======================= mma.sync GEMM ======================================
// C[m0:m0+256, cols] = Asplit[m0:m0+256, KE] @ Bsplit[:, KE]^T
// 512 threads = 16 warps (4m x 4n), warp tile 64x32, full-K A tile resident in
// SMEM, B streamed in 64-K chunks double-buffered with cp.async.
template <int KE, int NCH>
__global__ void __launch_bounds__(512, 1)
gemm_kernel(float* __restrict__ Cext, int dst_sel, int ldC, int nIters, int Mreal,
            const float* __restrict__ bias) {
    constexpr int B_OFF = NCH * A_CH_BYTES;
    extern __shared__ char smem[];
    uint32_t sb = smem_u32(smem);
    int tid = threadIdx.x, lid = tid & 31, wid = tid >> 5;
    int warp_m = wid >> 2, warp_n = wid & 3;
    int m0 = blockIdx.x * TM;
    int n0_base = blockIdx.y * nIters;      // in units of 128-col tiles

    float* C = dst_sel ? Cext : g_H;
    const __half* Ag = g_Asplit + (size_t)m0 * KE;

    // group 0: full A tile + B chunk 0 of first n-iter
    #pragma unroll
    for (int c = 0; c < NCH; c++) {
        for (int i = tid; i < TM * 8; i += 512) {
            int r = i >> 3, s = i & 7;
            cpa16(sb + c * A_CH_BYTES + SWZ128(r * 128 + s * 16),
                  Ag + (size_t)r * KE + c * KCH + s * 8);
        }
    }
    {
        const __half* Bg = g_Bsplit + (size_t)(n0_base * 128) * KE;
        for (int i = tid; i < 128 * 8; i += 512) {
            int r = i >> 3, s = i & 7;
            cpa16(sb + B_OFF + SWZ128(r * 128 + s * 16), Bg + (size_t)r * KE + s * 8);
        }
    }
    cpa_commit();

    const int a_row = warp_m * 64 + (lid & 7) + ((lid >> 3) & 1) * 8;
    const int a_ks  = (lid >> 4) * 8;
    const int b_row = warp_n * 32 + (lid & 7) + ((lid >> 4) & 1) * 8;
    const int b_ks  = ((lid >> 3) & 1) * 8;

    for (int it = 0; it < nIters; it++) {
        float acc[4][4][4];
        #pragma unroll
        for (int mi = 0; mi < 4; mi++)
            #pragma unroll
            for (int nj = 0; nj < 4; nj++)
                #pragma unroll
                for (int q = 0; q < 4; q++) acc[mi][nj][q] = 0.0f;

        for (int c = 0; c < NCH; c++) {
            int buf = c & 1;                       // NCH even -> parity stable
            int nc = c + 1, nit = it;
            if (nc == NCH) { nc = 0; nit = it + 1; }
            if (nit < nIters) {
                const __half* Bg = g_Bsplit + (size_t)((n0_base + nit) * 128) * KE + nc * KCH;
                uint32_t bb = sb + B_OFF + (buf ^ 1) * B_CH_BYTES;
                for (int i = tid; i < 128 * 8; i += 512) {
                    int r = i >> 3, s = i & 7;
                    cpa16(bb + SWZ128(r * 128 + s * 16), Bg + (size_t)r * KE + s * 8);
                }
            }
            cpa_commit();
            cpa_wait1();
            __syncthreads();

            uint32_t Ab = sb + c * A_CH_BYTES;
            uint32_t Bb = sb + B_OFF + buf * B_CH_BYTES;
            #pragma unroll
            for (int ks = 0; ks < 4; ks++) {
                uint32_t a[4][4], b[2][4];
                #pragma unroll
                for (int mi = 0; mi < 4; mi++)
                    ldmA4(a[mi], Ab + SWZ128((a_row + mi * 16) * 128 + (a_ks + ks * 16) * 2));
                #pragma unroll
                for (int bi = 0; bi < 2; bi++)
                    ldmA4(b[bi], Bb + SWZ128((b_row + bi * 16) * 128 + (b_ks + ks * 16) * 2));
                #pragma unroll
                for (int mi = 0; mi < 4; mi++)
                    #pragma unroll
                    for (int nj = 0; nj < 4; nj++)
                        mma16816(acc[mi][nj], a[mi], b[nj >> 1][(nj & 1) * 2],
                                 b[nj >> 1][(nj & 1) * 2 + 1]);
            }
            __syncthreads();
        }

        int n0 = (n0_base + it) * 128;
        #pragma unroll
        for (int mi = 0; mi < 4; mi++) {
            int r0 = m0 + warp_m * 64 + mi * 16 + (lid >> 2);
            #pragma unroll
            for (int nj = 0; nj < 4; nj++) {
                int col = n0 + warp_n * 32 + nj * 8 + ((lid & 3) << 1);
                float bx = bias ? bias[col] : 0.0f;
                float by = bias ? bias[col + 1] : 0.0f;
                if (r0 < Mreal) {
                    float2 o = {acc[mi][nj][0] + bx, acc[mi][nj][1] + by};
                    *(float2*)(C + (size_t)r0 * ldC + col) = o;
                }
                if (r0 + 8 < Mreal) {
                    float2 o = {acc[mi][nj][2] + bx, acc[mi][nj][3] + by};
                    *(float2*)(C + (size_t)(r0 + 8) * ldC + col) = o;
                }
            }
        }
    }
}

// ======================= SpMM + fused hi/lo split ===========================
// X[dst] = relu( dinv^2 * H[dst] + sum w_e H[src] + bias ); write split(X)
// directly to g_Asplit (KOUT=384: [hi|hi|lo], KOUT=256: [hi|lo]).
template <int KOUT>
__global__ void k_spmm(const float* __restrict__ bias) {
    int gw = (blockIdx.x * blockDim.x + threadIdx.x) >> 5;
    int lane = threadIdx.x & 31;
    if (gw >= NN) return;
    const float4* H4 = (const float4*)g_H;
    float di = g_dinv[gw];
    float s = di * di;
    float4 acc = H4[(size_t)gw * 32 + lane];
    acc.x *= s; acc.y *= s; acc.z *= s; acc.w *= s;
    int start = g_colptr[gw];
    int len = g_cnt[gw];
    int j = 0;
    for (; j + 2 <= len; j += 2) {                  // 2-deep MLP
        int e0 = start + j, e1 = e0 + 1;
        int s0 = g_esrc[e0], s1 = g_esrc[e1];
        float w0 = g_eww[e0], w1 = g_eww[e1];
        float4 v0 = H4[(size_t)s0 * 32 + lane];
        float4 v1 = H4[(size_t)s1 * 32 + lane];
        acc.x += w0 * v0.x + w1 * v1.x;
        acc.y += w0 * v0.y + w1 * v1.y;
        acc.z += w0 * v0.z + w1 * v1.z;
        acc.w += w0 * v0.w + w1 * v1.w;
    }
    if (j < len) {
        int e = start + j;
        int src = g_esrc[e];
        float w = g_eww[e];
        float4 v = H4[(size_t)src * 32 + lane];
        acc.x += w * v.x; acc.y += w * v.y; acc.z += w * v.z; acc.w += w * v.w;
    }
    float4 b4 = ((const float4*)bias)[lane];
    acc.x = fmaxf(acc.x + b4.x, 0.0f);
    acc.y = fmaxf(acc.y + b4.y, 0.0f);
    acc.z = fmaxf(acc.z + b4.z, 0.0f);
    acc.w = fmaxf(acc.w + b4.w, 0.0f);

    __half h0 = __float2half(acc.x), h1 = __float2half(acc.y);
    __half h2 = __float2half(acc.z), h3 = __float2half(acc.w);
    __half l0 = __float2half(acc.x - __half2float(h0));
    __half l1 = __float2half(acc.y - __half2float(h1));
    __half l2 = __float2half(acc.z - __half2float(h2));
    __half l3 = __float2half(acc.w - __half2float(h3));
    __half2 hp0 = __halves2half2(h0, h1), hp1 = __halves2half2(h2, h3);
    __half2 lp0 = __halves2half2(l0, l1), lp1 = __halves2half2(l2, l3);
    uint2 hv = {*(uint32_t*)&hp0, *(uint32_t*)&hp1};
    uint2 lv = {*(uint32_t*)&lp0, *(uint32_t*)&lp1};
    size_t base = (size_t)gw * KOUT + lane * 4;
    *(uint2*)(g_Asplit + base) = hv;
    if (KOUT == KE3) {
        *(uint2*)(g_Asplit + base + 128) = hv;
        *(uint2*)(g_Asplit + base + 256) = lv;
    } else {
        *(uint2*)(g_Asplit + base + 128) = lv;
    }
}

// ======================= launch =============================================
extern "C" void kernel_launch(void* const* d_in, const int* in_sizes, int n_in,
                              void* d_out, int out_size) {
    const int*   node_idx = (const int*)d_in[0];
    const int*   ei       = (const int*)d_in[1];
    const float* ew       = (const float*)d_in[2];
    const float* emb      = (const float*)d_in[3];
    const float* W1       = (const float*)d_in[4];
    const float* b1       = (const float*)d_in[5];
    const float* W2       = (const float*)d_in[6];
    const float* b2       = (const float*)d_in[7];
    const float* Wout     = (const float*)d_in[8];
    const float* bout     = (const float*)d_in[9];
    float* out = (float*)d_out;
    const int* row = ei;
    const int* col = ei + EE;

    constexpr int SMEM_L = 6 * A_CH_BYTES + 2 * B_CH_BYTES;   // 229376
    constexpr int SMEM_F = 4 * A_CH_BYTES + 2 * B_CH_BYTES;   // 163840
    cudaFuncSetAttribute(gemm_kernel<KE3, 6>,
                         cudaFuncAttributeMaxDynamicSharedMemorySize, SMEM_L);
    cudaFuncSetAttribute(gemm_kernel<KE2, 4>,
                         cudaFuncAttributeMaxDynamicSharedMemorySize, SMEM_F);

    // preprocessing: CSC by destination + symmetric norm
    k_init<<<(NN + 255) / 256, 256>>>();
    k_hist<<<(EE + 255) / 256, 256>>>(row, col, ew);
    k_dinv<<<(NN + 255) / 256, 256>>>();
    k_scanA<<<NBLK_SCAN, 1024>>>();
    k_scanB<<<1, 1>>>();
    k_scanC<<<NBLK_SCAN, 1024>>>();
    k_fill<<<(EE + 255) / 256, 256>>>(row, col, ew);

    const int gemm_grid = MPAD / TM;                 // 391
    const int spmm_grid = (NN + 7) / 8;

    // layer 1: x@W1 (3-term), aggregate+relu -> split (3-term)
    k_splitA1<<<4096, 256>>>(emb, node_idx);
    k_splitB<<<64, 256>>>(W1, FEAT, 1);
    gemm_kernel<KE3, 6><<<gemm_grid, 512, SMEM_L>>>(nullptr, 0, FEAT, 1, MPAD, nullptr);
    k_spmm<KE3><<<spmm_grid, 256>>>(b1);

    // layer 2: (3-term), aggregate+relu -> split (2-term)
    k_splitB<<<64, 256>>>(W2, FEAT, 1);
    gemm_kernel<KE3, 6><<<gemm_grid, 512, SMEM_L>>>(nullptr, 0, FEAT, 1, MPAD, nullptr);
    k_spmm<KE2><<<spmm_grid, 256>>>(b2);

    // output layer: 2-term (exact x@Whi + x@ -> only W rounding error)
    k_splitB<<<1024, 256>>>(Wout, NLAB, 0);
    gemm_kernel<KE2, 4><<<dim3(gemm_grid, 2), 512, SMEM_F>>>(out, 1, NLAB, 8, NN, bout);
}

// round 6
// speedup vs baseline: 1.3011x; 1.0369x over previous
#include <cuda_runtime.h>
#include <cuda_fp16.h>
#include <cstdint>

#define NN 100000
#define EE 1000000
#define FEAT 128
#define NLAB 2048
#define MPAD 100096            // 391 * 256
#define KE2 256                // 2-term: A=[hi|lo], B=[Whi|Whi]
#define NBLK_SCAN 98

// GEMM tiling
#define TM 256
#define KCH 64
#define A_CH_BYTES (TM * 128)          // 32768
#define B_CH_BYTES (128 * 128)         // 16384

// ======================= device scratch =====================================
static __device__ __align__(16) __half g_Asplit[(size_t)MPAD * KE2]; // 51.2 MB
static __device__ __align__(16) __half g_Bsplit[(size_t)NLAB * KE2]; //  1.0 MB
static __device__ __align__(16) float g_H[(size_t)MPAD * FEAT];      // 51.2 MB
static __device__ float g_deg[NN];
static __device__ float g_dinv[NN];
static __device__ int   g_cnt[NN];
static __device__ int   g_colptr[NN];
static __device__ int   g_cursor[NN];
static __device__ int   g_bsum[128];
static __device__ int   g_bofs[128];
static __device__ int   g_esrc[EE];
static __device__ float g_eww[EE];

// ======================= helpers ============================================
__device__ __forceinline__ uint32_t smem_u32(const void* p) {
    uint32_t a;
    asm("{ .reg .u64 t; cvta.to.shared.u64 t, %1; cvt.u32.u64 %0, t; }" : "=r"(a) : "l"(p));
    return a;
}
#define SWZ128(x) ((x) ^ (((x) >> 3) & 0x70))

__device__ __forceinline__ void cpa16(uint32_t s, const void* g) {
    asm volatile("cp.async.cg.shared.global [%0], [%1], 16;"
                 :: "r"(s), "l"(__cvta_generic_to_global(g)) : "memory");
}
__device__ __forceinline__ void cpa_commit() {
    asm volatile("cp.async.commit_group;" ::: "memory");
}
__device__ __forceinline__ void cpa_wait1() {
    asm volatile("cp.async.wait_group 1;" ::: "memory");
}
__device__ __forceinline__ void ldmA4(uint32_t* r, uint32_t addr) {
    asm volatile("ldmatrix.sync.aligned.m8n8.x4.shared.b16 {%0,%1,%2,%3}, [%4];"
                 : "=r"(r[0]), "=r"(r[1]), "=r"(r[2]), "=r"(r[3]) : "r"(addr));
}
__device__ __forceinline__ void mma16816(float* d, const uint32_t* a, uint32_t b0, uint32_t b1) {
    asm volatile(
        "mma.sync.aligned.m16n8k16.row.col.f32.f16.f16.f32 "
        "{%0,%1,%2,%3}, {%4,%5,%6,%7}, {%8,%9}, {%0,%1,%2,%3};"
        : "+f"(d[0]), "+f"(d[1]), "+f"(d[2]), "+f"(d[3])
        : "r"(a[0]), "r"(a[1]), "r"(a[2]), "r"(a[3]), "r"(b0), "r"(b1));
}

// ======================= graph preprocessing ================================
__global__ void k_init() {
    int i = blockIdx.x * blockDim.x + threadIdx.x;
    if (i < NN) { g_deg[i] = 1.0f; g_cnt[i] = 0; }
}
__global__ void k_hist(const int* __restrict__ row, const int* __restrict__ col,
                       const float* __restrict__ ew) {
    int e = blockIdx.x * blockDim.x + threadIdx.x;
    if (e < EE) {
        int c = col[e];
        atomicAdd(&g_deg[c], ew[e]);
        atomicAdd(&g_cnt[c], 1);
    }
}
__global__ void k_dinv() {
    int i = blockIdx.x * blockDim.x + threadIdx.x;
    if (i < NN) g_dinv[i] = rsqrtf(g_deg[i]);
}
__global__ void k_scanA() {
    __shared__ int s[1024];
    int t = threadIdx.x;
    int i = blockIdx.x * 1024 + t;
    int v = (i < NN) ? g_cnt[i] : 0;
    s[t] = v;
    __syncthreads();
    for (int off = 1; off < 1024; off <<= 1) {
        int add = (t >= off) ? s[t - off] : 0;
        __syncthreads();
        s[t] += add;
        __syncthreads();
    }
    if (i < NN) g_colptr[i] = s[t] - v;
    if (t == 1023) g_bsum[blockIdx.x] = s[1023];
}
__global__ void k_scanB() {
    int acc = 0;
    for (int b = 0; b < NBLK_SCAN; b++) { g_bofs[b] = acc; acc += g_bsum[b]; }
}
__global__ void k_scanC() {
    int i = blockIdx.x * 1024 + threadIdx.x;
    if (i < NN) {
        int ex = g_colptr[i] + g_bofs[blockIdx.x];
        g_colptr[i] = ex;
        g_cursor[i] = ex;
    }
}
__global__ void k_fill(const int* __restrict__ row, const int* __restrict__ col,
                       const float* __restrict__ ew) {
    int e = blockIdx.x * blockDim.x + threadIdx.x;
    if (e < EE) {
        int c = col[e], r = row[e];
        int pos = atomicAdd(&g_cursor[c], 1);
        g_esrc[pos] = r;
        g_eww[pos] = g_dinv[r] * ew[e] * g_dinv[c];
    }
}

// ======================= splits (2-term) ====================================
// A' = [hi | lo] (near-exact x), B' = [Whi | Whi] -> computes x @ Whi
__global__ void k_splitA1(const float* __restrict__ emb, const int* __restrict__ idx) {
    const size_t total = (size_t)NN * FEAT;
    for (size_t i = (size_t)blockIdx.x * blockDim.x + threadIdx.x; i < total;
         i += (size_t)gridDim.x * blockDim.x) {
        int m = (int)(i >> 7), k = (int)(i & 127);
        float v = emb[(size_t)idx[m] * FEAT + k];
        __half hi = __float2half(v);
        __half lo = __float2half(v - __half2float(hi));
        size_t base = (size_t)m * KE2;
        g_Asplit[base + k] = hi;
        g_Asplit[base + 128 + k] = lo;
    }
}
__global__ void k_splitB(const float* __restrict__ W, int ncols) {
    int total = ncols * FEAT;
    for (int i = blockIdx.x * blockDim.x + threadIdx.x; i < total;
         i += gridDim.x * blockDim.x) {
        int nr = i >> 7, k = i & 127;
        float v = W[(size_t)k * ncols + nr];
        __half hi = __float2half(v);
        size_t base = (size_t)nr * KE2;
        g_Bsplit[base + k] = hi;
        g_Bsplit[base + 128 + k] = hi;
    }
}

// ======================= mma.sync GEMM (R3-proven body) =====================
// C[m0:m0+256, cols] = Asplit[m0:m0+256, KE] @ Bsplit[:, KE]^T
// 512 threads = 16 warps (4m x 4n), warp tile 64x32, full-K A resident in SMEM,
// B streamed in 64-K chunks double-buffered with cp.async.
template <int KE, int NCH>
__global__ void __launch_bounds__(512, 1)
gemm_kernel(float* __restrict__ Cext, int dst_sel, int ldC, int nIters, int Mreal,
            const float* __restrict__ bias) {
    constexpr int B_OFF = NCH * A_CH_BYTES;
    extern __shared__ char smem[];
    uint32_t sb = smem_u32(smem);
    int tid = threadIdx.x, lid = tid & 31, wid = tid >> 5;
    int warp_m = wid >> 2, warp_n = wid & 3;
    int m0 = blockIdx.x * TM;
    int n0_base = blockIdx.y * nIters;      // units of 128-col tiles

    float* C = dst_sel ? Cext : g_H;
    const __half* Ag = g_Asplit + (size_t)m0 * KE;

    // group 0: full A tile + B chunk 0 of first n-iter
    #pragma unroll
    for (int c = 0; c < NCH; c++) {
        for (int i = tid; i < TM * 8; i += 512) {
            int r = i >> 3, s = i & 7;
            cpa16(sb + c * A_CH_BYTES + SWZ128(r * 128 + s * 16),
                  Ag + (size_t)r * KE + c * KCH + s * 8);
        }
    }
    {
        const __half* Bg = g_Bsplit + (size_t)(n0_base * 128) * KE;
        for (int i = tid; i < 128 * 8; i += 512) {
            int r = i >> 3, s = i & 7;
            cpa16(sb + B_OFF + SWZ128(r * 128 + s * 16), Bg + (size_t)r * KE + s * 8);
        }
    }
    cpa_commit();

    const int a_row = warp_m * 64 + (lid & 7) + ((lid >> 3) & 1) * 8;
    const int a_ks  = (lid >> 4) * 8;
    const int b_row = warp_n * 32 + (lid & 7) + ((lid >> 4) & 1) * 8;
    const int b_ks  = ((lid >> 3) & 1) * 8;

    for (int it = 0; it < nIters; it++) {
        float acc[4][4][4];
        #pragma unroll
        for (int mi = 0; mi < 4; mi++)
            #pragma unroll
            for (int nj = 0; nj < 4; nj++)
                #pragma unroll
                for (int q = 0; q < 4; q++) acc[mi][nj][q] = 0.0f;

        for (int c = 0; c < NCH; c++) {
            int buf = c & 1;                       // NCH even -> parity stable
            int nc = c + 1, nit = it;
            if (nc == NCH) { nc = 0; nit = it + 1; }
            if (nit < nIters) {
                const __half* Bg = g_Bsplit + (size_t)((n0_base + nit) * 128) * KE + nc * KCH;
                uint32_t bb = sb + B_OFF + (buf ^ 1) * B_CH_BYTES;
                for (int i = tid; i < 128 * 8; i += 512) {
                    int r = i >> 3, s = i & 7;
                    cpa16(bb + SWZ128(r * 128 + s * 16), Bg + (size_t)r * KE + s * 8);
                }
            }
            cpa_commit();
            cpa_wait1();
            __syncthreads();

            uint32_t Ab = sb + c * A_CH_BYTES;
            uint32_t Bb = sb + B_OFF + buf * B_CH_BYTES;
            #pragma unroll
            for (int ks = 0; ks < 4; ks++) {
                uint32_t a[4][4], b[2][4];
                #pragma unroll
                for (int mi = 0; mi < 4; mi++)
                    ldmA4(a[mi], Ab + SWZ128((a_row + mi * 16) * 128 + (a_ks + ks * 16) * 2));
                #pragma unroll
                for (int bi = 0; bi < 2; bi++)
                    ldmA4(b[bi], Bb + SWZ128((b_row + bi * 16) * 128 + (b_ks + ks * 16) * 2));
                #pragma unroll
                for (int mi = 0; mi < 4; mi++)
                    #pragma unroll
                    for (int nj = 0; nj < 4; nj++)
                        mma16816(acc[mi][nj], a[mi], b[nj >> 1][(nj & 1) * 2],
                                 b[nj >> 1][(nj & 1) * 2 + 1]);
            }
            __syncthreads();
        }

        int n0 = (n0_base + it) * 128;
        #pragma unroll
        for (int mi = 0; mi < 4; mi++) {
            int r0 = m0 + warp_m * 64 + mi * 16 + (lid >> 2);
            #pragma unroll
            for (int nj = 0; nj < 4; nj++) {
                int col = n0 + warp_n * 32 + nj * 8 + ((lid & 3) << 1);
                float bx = bias ? bias[col] : 0.0f;
                float by = bias ? bias[col + 1] : 0.0f;
                if (r0 < Mreal) {
                    float2 o = {acc[mi][nj][0] + bx, acc[mi][nj][1] + by};
                    *(float2*)(C + (size_t)r0 * ldC + col) = o;
                }
                if (r0 + 8 < Mreal) {
                    float2 o = {acc[mi][nj][2] + bx, acc[mi][nj][3] + by};
                    *(float2*)(C + (size_t)(r0 + 8) * ldC + col) = o;
                }
            }
        }
    }
}

// ======================= SpMM + fused hi/lo split ===========================
// X[dst] = relu( dinv^2 * H[dst] + sum w_e H[src] + bias ); write [hi|lo]
// directly into g_Asplit.
__global__ void k_spmm(const float* __restrict__ bias) {
    int gw = (blockIdx.x * blockDim.x + threadIdx.x) >> 5;
    int lane = threadIdx.x & 31;
    if (gw >= NN) return;
    const float4* H4 = (const float4*)g_H;
    float di = g_dinv[gw];
    float s = di * di;
    float4 acc = H4[(size_t)gw * 32 + lane];
    acc.x *= s; acc.y *= s; acc.z *= s; acc.w *= s;
    int start = g_colptr[gw];
    int len = g_cnt[gw];
    int j = 0;
    for (; j + 2 <= len; j += 2) {
        int e0 = start + j, e1 = e0 + 1;
        int s0 = g_esrc[e0], s1 = g_esrc[e1];
        float w0 = g_eww[e0], w1 = g_eww[e1];
        float4 v0 = H4[(size_t)s0 * 32 + lane];
        float4 v1 = H4[(size_t)s1 * 32 + lane];
        acc.x += w0 * v0.x + w1 * v1.x;
        acc.y += w0 * v0.y + w1 * v1.y;
        acc.z += w0 * v0.z + w1 * v1.z;
        acc.w += w0 * v0.w + w1 * v1.w;
    }
    if (j < len) {
        int e = start + j;
        int src = g_esrc[e];
        float w = g_eww[e];
        float4 v = H4[(size_t)src * 32 + lane];
        acc.x += w * v.x; acc.y += w * v.y; acc.z += w * v.z; acc.w += w * v.w;
    }
    float4 b4 = ((const float4*)bias)[lane];
    acc.x = fmaxf(acc.x + b4.x, 0.0f);
    acc.y = fmaxf(acc.y + b4.y, 0.0f);
    acc.z = fmaxf(acc.z + b4.z, 0.0f);
    acc.w = fmaxf(acc.w + b4.w, 0.0f);

    __half h0 = __float2half(acc.x), h1 = __float2half(acc.y);
    __half h2 = __float2half(acc.z), h3 = __float2half(acc.w);
    __half l0 = __float2half(acc.x - __half2float(h0));
    __half l1 = __float2half(acc.y - __half2float(h1));
    __half l2 = __float2half(acc.z - __half2float(h2));
    __half l3 = __float2half(acc.w - __half2float(h3));
    __half2 hp0 = __halves2half2(h0, h1), hp1 = __halves2half2(h2, h3);
    __half2 lp0 = __halves2half2(l0, l1), lp1 = __halves2half2(l2, l3);
    uint2 hv = {*(uint32_t*)&hp0, *(uint32_t*)&hp1};
    uint2 lv = {*(uint32_t*)&lp0, *(uint32_t*)&lp1};
    size_t base = (size_t)gw * KE2 + lane * 4;
    *(uint2*)(g_Asplit + base) = hv;
    *(uint2*)(g_Asplit + base + 128) = lv;
}

// ======================= launch =============================================
extern "C" void kernel_launch(void* const* d_in, const int* in_sizes, int n_in,
                              void* d_out, int out_size) {
    const int*   node_idx = (const int*)d_in[0];
    const int*   ei       = (const int*)d_in[1];
    const float* ew       = (const float*)d_in[2];
    const float* emb      = (const float*)d_in[3];
    const float* W1       = (const float*)d_in[4];
    const float* b1       = (const float*)d_in[5];
    const float* W2       = (const float*)d_in[6];
    const float* b2       = (const float*)d_in[7];
    const float* Wout     = (const float*)d_in[8];
    const float* bout     = (const float*)d_in[9];
    float* out = (float*)d_out;
    const int* row = ei;
    const int* col = ei + EE;

    constexpr int SMEM_F = 4 * A_CH_BYTES + 2 * B_CH_BYTES;   // 163840
    cudaFuncSetAttribute(gemm_kernel<KE2, 4>,
                         cudaFuncAttributeMaxDynamicSharedMemorySize, SMEM_F);

    // preprocessing: CSC by destination + symmetric norm
    k_init<<<(NN + 255) / 256, 256>>>();
    k_hist<<<(EE + 255) / 256, 256>>>(row, col, ew);
    k_dinv<<<(NN + 255) / 256, 256>>>();
    k_scanA<<<NBLK_SCAN, 1024>>>();
    k_scanB<<<1, 1>>>();
    k_scanC<<<NBLK_SCAN, 1024>>>();
    k_fill<<<(EE + 255) / 256, 256>>>(row, col, ew);

    const int gemm_grid = MPAD / TM;                 // 391
    const int spmm_grid = (NN + 7) / 8;

    // layer 1
    k_splitA1<<<4096, 256>>>(emb, node_idx);
    k_splitB<<<64, 256>>>(W1, FEAT);
    gemm_kernel<KE2, 4><<<gemm_grid, 512, SMEM_F>>>(nullptr, 0, FEAT, 1, MPAD, nullptr);
    k_spmm<<<spmm_grid, 256>>>(b1);

    // layer 2
    k_splitB<<<64, 256>>>(W2, FEAT);
    gemm_kernel<KE2, 4><<<gemm_grid, 512, SMEM_F>>>(nullptr, 0, FEAT, 1, MPAD, nullptr);
    k_spmm<<<spmm_grid, 256>>>(b2);

    // output layer: grid (391, 2), 8 n-iters each
    k_splitB<<<1024, 256>>>(Wout, NLAB);
    gemm_kernel<KE2, 4><<<dim3(gemm_grid, 2), 512, SMEM_F>>>(out, 1, NLAB, 8, NN, bout);
}

// round 7
// speedup vs baseline: 1.6177x; 1.2434x over previous
#include <cuda_runtime.h>
#include <cuda_fp16.h>
#include <cstdint>

#define NN 100000
#define EE 1000000
#define FEAT 128
#define NLAB 2048
#define MPAD 100096            // 391 * 256
#define KE2 256                // 2-term: A=[hi|lo], B=[Whi|Whi]
#define NBLK_SCAN 98

// GEMM tiling
#define TM 256
#define KCH 64
#define A_CH_BYTES (TM * 128)          // 32768
#define B_CH_BYTES (128 * 128)         // 16384

// ======================= device scratch =====================================
static __device__ __align__(16) __half g_Asplit[(size_t)MPAD * KE2]; // 51.2 MB
static __device__ __align__(16) __half g_Bsplit[(size_t)NLAB * KE2]; //  1.0 MB
static __device__ __align__(16) float g_H[(size_t)MPAD * FEAT];      // 51.2 MB
static __device__ float g_deg[NN];
static __device__ float g_dinv[NN];
static __device__ int   g_cnt[NN];
static __device__ int   g_colptr[NN];
static __device__ int   g_cursor[NN];
static __device__ int   g_bsum[128];
static __device__ int   g_bofs[128];
static __device__ int   g_esrc[EE];
static __device__ float g_eww[EE];

// ======================= helpers ============================================
__device__ __forceinline__ uint32_t smem_u32(const void* p) {
    uint32_t a;
    asm("{ .reg .u64 t; cvta.to.shared.u64 t, %1; cvt.u32.u64 %0, t; }" : "=r"(a) : "l"(p));
    return a;
}
#define SWZ128(x) ((x) ^ (((x) >> 3) & 0x70))

__device__ __forceinline__ void cpa16(uint32_t s, const void* g) {
    asm volatile("cp.async.cg.shared.global [%0], [%1], 16;"
                 :: "r"(s), "l"(__cvta_generic_to_global(g)) : "memory");
}
__device__ __forceinline__ void cpa_commit() {
    asm volatile("cp.async.commit_group;" ::: "memory");
}
__device__ __forceinline__ void cpa_wait1() {
    asm volatile("cp.async.wait_group 1;" ::: "memory");
}
__device__ __forceinline__ void ldmA4(uint32_t* r, uint32_t addr) {
    asm volatile("ldmatrix.sync.aligned.m8n8.x4.shared.b16 {%0,%1,%2,%3}, [%4];"
                 : "=r"(r[0]), "=r"(r[1]), "=r"(r[2]), "=r"(r[3]) : "r"(addr));
}
__device__ __forceinline__ void mma16816(float* d, const uint32_t* a, uint32_t b0, uint32_t b1) {
    asm volatile(
        "mma.sync.aligned.m16n8k16.row.col.f32.f16.f16.f32 "
        "{%0,%1,%2,%3}, {%4,%5,%6,%7}, {%8,%9}, {%0,%1,%2,%3};"
        : "+f"(d[0]), "+f"(d[1]), "+f"(d[2]), "+f"(d[3])
        : "r"(a[0]), "r"(a[1]), "r"(a[2]), "r"(a[3]), "r"(b0), "r"(b1));
}

// ======================= graph preprocessing ================================
__global__ void k_init() {
    int i = blockIdx.x * blockDim.x + threadIdx.x;
    if (i < NN) { g_deg[i] = 1.0f; g_cnt[i] = 0; }
}
__global__ void k_hist(const int* __restrict__ row, const int* __restrict__ col,
                       const float* __restrict__ ew) {
    int e = blockIdx.x * blockDim.x + threadIdx.x;
    if (e < EE) {
        int c = col[e];
        atomicAdd(&g_deg[c], ew[e]);
        atomicAdd(&g_cnt[c], 1);
    }
}
__global__ void k_dinv() {
    int i = blockIdx.x * blockDim.x + threadIdx.x;
    if (i < NN) g_dinv[i] = rsqrtf(g_deg[i]);
}
__global__ void k_scanA() {
    __shared__ int s[1024];
    int t = threadIdx.x;
    int i = blockIdx.x * 1024 + t;
    int v = (i < NN) ? g_cnt[i] : 0;
    s[t] = v;
    __syncthreads();
    for (int off = 1; off < 1024; off <<= 1) {
        int add = (t >= off) ? s[t - off] : 0;
        __syncthreads();
        s[t] += add;
        __syncthreads();
    }
    if (i < NN) g_colptr[i] = s[t] - v;
    if (t == 1023) g_bsum[blockIdx.x] = s[1023];
}
__global__ void k_scanB() {
    int acc = 0;
    for (int b = 0; b < NBLK_SCAN; b++) { g_bofs[b] = acc; acc += g_bsum[b]; }
}
__global__ void k_scanC() {
    int i = blockIdx.x * 1024 + threadIdx.x;
    if (i < NN) {
        int ex = g_colptr[i] + g_bofs[blockIdx.x];
        g_colptr[i] = ex;
        g_cursor[i] = ex;
    }
}
__global__ void k_fill(const int* __restrict__ row, const int* __restrict__ col,
                       const float* __restrict__ ew) {
    int e = blockIdx.x * blockDim.x + threadIdx.x;
    if (e < EE) {
        int c = col[e], r = row[e];
        int pos = atomicAdd(&g_cursor[c], 1);
        g_esrc[pos] = r;
        g_eww[pos] = g_dinv[r] * ew[e] * g_dinv[c];
    }
}

// ======================= splits =============================================
// Layer-1 A: [hi | lo] stride 256
__global__ void k_splitA1(const float* __restrict__ emb, const int* __restrict__ idx) {
    const size_t total = (size_t)NN * FEAT;
    for (size_t i = (size_t)blockIdx.x * blockDim.x + threadIdx.x; i < total;
         i += (size_t)gridDim.x * blockDim.x) {
        int m = (int)(i >> 7), k = (int)(i & 127);
        float v = emb[(size_t)idx[m] * FEAT + k];
        __half hi = __float2half(v);
        __half lo = __float2half(v - __half2float(hi));
        size_t base = (size_t)m * KE2;
        g_Asplit[base + k] = hi;
        g_Asplit[base + 128 + k] = lo;
    }
}
// TWO_TERM: [Whi | Whi] stride 256; else single [Whi] stride 128
template <bool TWO_TERM>
__global__ void k_splitB(const float* __restrict__ W, int ncols) {
    int total = ncols * FEAT;
    for (int i = blockIdx.x * blockDim.x + threadIdx.x; i < total;
         i += gridDim.x * blockDim.x) {
        int nr = i >> 7, k = i & 127;
        float v = W[(size_t)k * ncols + nr];
        __half hi = __float2half(v);
        if (TWO_TERM) {
            size_t base = (size_t)nr * KE2;
            g_Bsplit[base + k] = hi;
            g_Bsplit[base + 128 + k] = hi;
        } else {
            g_Bsplit[(size_t)nr * 128 + k] = hi;
        }
    }
}

// ======================= mma.sync GEMM (R3-proven body) =====================
// C[m0:m0+256, cols] = A[m0:m0+256, 0:KE] @ B[:, 0:KE]^T
// A row stride LDA, B row stride LDB (elements). 512 threads = 16 warps
// (4m x 4n), warp tile 64x32, full-K A resident in SMEM, B streamed in 64-K
// chunks double-buffered with cp.async.
template <int KE, int NCH, int LDA, int LDB>
__global__ void __launch_bounds__(512, 1)
gemm_kernel(float* __restrict__ Cext, int dst_sel, int ldC, int nIters, int Mreal,
            const float* __restrict__ bias) {
    constexpr int B_OFF = NCH * A_CH_BYTES;
    extern __shared__ char smem[];
    uint32_t sb = smem_u32(smem);
    int tid = threadIdx.x, lid = tid & 31, wid = tid >> 5;
    int warp_m = wid >> 2, warp_n = wid & 3;
    int m0 = blockIdx.x * TM;
    int n0_base = blockIdx.y * nIters;      // units of 128-col tiles

    float* C = dst_sel ? Cext : g_H;
    const __half* Ag = g_Asplit + (size_t)m0 * LDA;

    // group 0: full A tile + B chunk 0 of first n-iter
    #pragma unroll
    for (int c = 0; c < NCH; c++) {
        for (int i = tid; i < TM * 8; i += 512) {
            int r = i >> 3, s = i & 7;
            cpa16(sb + c * A_CH_BYTES + SWZ128(r * 128 + s * 16),
                  Ag + (size_t)r * LDA + c * KCH + s * 8);
        }
    }
    {
        const __half* Bg = g_Bsplit + (size_t)(n0_base * 128) * LDB;
        for (int i = tid; i < 128 * 8; i += 512) {
            int r = i >> 3, s = i & 7;
            cpa16(sb + B_OFF + SWZ128(r * 128 + s * 16), Bg + (size_t)r * LDB + s * 8);
        }
    }
    cpa_commit();

    const int a_row = warp_m * 64 + (lid & 7) + ((lid >> 3) & 1) * 8;
    const int a_ks  = (lid >> 4) * 8;
    const int b_row = warp_n * 32 + (lid & 7) + ((lid >> 4) & 1) * 8;
    const int b_ks  = ((lid >> 3) & 1) * 8;

    for (int it = 0; it < nIters; it++) {
        float acc[4][4][4];
        #pragma unroll
        for (int mi = 0; mi < 4; mi++)
            #pragma unroll
            for (int nj = 0; nj < 4; nj++)
                #pragma unroll
                for (int q = 0; q < 4; q++) acc[mi][nj][q] = 0.0f;

        for (int c = 0; c < NCH; c++) {
            int buf = c & 1;                       // NCH even -> parity stable
            int nc = c + 1, nit = it;
            if (nc == NCH) { nc = 0; nit = it + 1; }
            if (nit < nIters) {
                const __half* Bg = g_Bsplit + (size_t)((n0_base + nit) * 128) * LDB + nc * KCH;
                uint32_t bb = sb + B_OFF + (buf ^ 1) * B_CH_BYTES;
                for (int i = tid; i < 128 * 8; i += 512) {
                    int r = i >> 3, s = i & 7;
                    cpa16(bb + SWZ128(r * 128 + s * 16), Bg + (size_t)r * LDB + s * 8);
                }
            }
            cpa_commit();
            cpa_wait1();
            __syncthreads();

            uint32_t Ab = sb + c * A_CH_BYTES;
            uint32_t Bb = sb + B_OFF + buf * B_CH_BYTES;
            #pragma unroll
            for (int ks = 0; ks < 4; ks++) {
                uint32_t a[4][4], b[2][4];
                #pragma unroll
                for (int mi = 0; mi < 4; mi++)
                    ldmA4(a[mi], Ab + SWZ128((a_row + mi * 16) * 128 + (a_ks + ks * 16) * 2));
                #pragma unroll
                for (int bi = 0; bi < 2; bi++)
                    ldmA4(b[bi], Bb + SWZ128((b_row + bi * 16) * 128 + (b_ks + ks * 16) * 2));
                #pragma unroll
                for (int mi = 0; mi < 4; mi++)
                    #pragma unroll
                    for (int nj = 0; nj < 4; nj++)
                        mma16816(acc[mi][nj], a[mi], b[nj >> 1][(nj & 1) * 2],
                                 b[nj >> 1][(nj & 1) * 2 + 1]);
            }
            __syncthreads();
        }

        int n0 = (n0_base + it) * 128;
        #pragma unroll
        for (int mi = 0; mi < 4; mi++) {
            int r0 = m0 + warp_m * 64 + mi * 16 + (lid >> 2);
            #pragma unroll
            for (int nj = 0; nj < 4; nj++) {
                int col = n0 + warp_n * 32 + nj * 8 + ((lid & 3) << 1);
                float bx = bias ? bias[col] : 0.0f;
                float by = bias ? bias[col + 1] : 0.0f;
                if (r0 < Mreal) {
                    float2 o = {acc[mi][nj][0] + bx, acc[mi][nj][1] + by};
                    *(float2*)(C + (size_t)r0 * ldC + col) = o;
                }
                if (r0 + 8 < Mreal) {
                    float2 o = {acc[mi][nj][2] + bx, acc[mi][nj][3] + by};
                    *(float2*)(C + (size_t)(r0 + 8) * ldC + col) = o;
                }
            }
        }
    }
}

// ======================= SpMM + fused hi/lo split ===========================
// X[dst] = relu( dinv^2 * H[dst] + sum w_e H[src] + bias ); write [hi|lo]
// (or hi only) into g_Asplit at stride 256.
template <bool WRITE_LO>
__global__ void k_spmm(const float* __restrict__ bias) {
    int gw = (blockIdx.x * blockDim.x + threadIdx.x) >> 5;
    int lane = threadIdx.x & 31;
    if (gw >= NN) return;
    const float4* H4 = (const float4*)g_H;
    float di = g_dinv[gw];
    float s = di * di;
    float4 acc = H4[(size_t)gw * 32 + lane];
    acc.x *= s; acc.y *= s; acc.z *= s; acc.w *= s;
    int start = g_colptr[gw];
    int len = g_cnt[gw];
    int j = 0;
    for (; j + 2 <= len; j += 2) {
        int e0 = start + j, e1 = e0 + 1;
        int s0 = g_esrc[e0], s1 = g_esrc[e1];
        float w0 = g_eww[e0], w1 = g_eww[e1];
        float4 v0 = H4[(size_t)s0 * 32 + lane];
        float4 v1 = H4[(size_t)s1 * 32 + lane];
        acc.x += w0 * v0.x + w1 * v1.x;
        acc.y += w0 * v0.y + w1 * v1.y;
        acc.z += w0 * v0.z + w1 * v1.z;
        acc.w += w0 * v0.w + w1 * v1.w;
    }
    if (j < len) {
        int e = start + j;
        int src = g_esrc[e];
        float w = g_eww[e];
        float4 v = H4[(size_t)src * 32 + lane];
        acc.x += w * v.x; acc.y += w * v.y; acc.z += w * v.z; acc.w += w * v.w;
    }
    float4 b4 = ((const float4*)bias)[lane];
    acc.x = fmaxf(acc.x + b4.x, 0.0f);
    acc.y = fmaxf(acc.y + b4.y, 0.0f);
    acc.z = fmaxf(acc.z + b4.z, 0.0f);
    acc.w = fmaxf(acc.w + b4.w, 0.0f);

    __half h0 = __float2half(acc.x), h1 = __float2half(acc.y);
    __half h2 = __float2half(acc.z), h3 = __float2half(acc.w);
    __half2 hp0 = __halves2half2(h0, h1), hp1 = __halves2half2(h2, h3);
    uint2 hv = {*(uint32_t*)&hp0, *(uint32_t*)&hp1};
    size_t base = (size_t)gw * KE2 + lane * 4;
    *(uint2*)(g_Asplit + base) = hv;
    if (WRITE_LO) {
        __half l0 = __float2half(acc.x - __half2float(h0));
        __half l1 = __float2half(acc.y - __half2float(h1));
        __half l2 = __float2half(acc.z - __half2float(h2));
        __half l3 = __float2half(acc.w - __half2float(h3));
        __half2 lp0 = __halves2half2(l0, l1), lp1 = __halves2half2(l2, l3);
        uint2 lv = {*(uint32_t*)&lp0, *(uint32_t*)&lp1};
        *(uint2*)(g_Asplit + base + 128) = lv;
    }
}

// ======================= launch =============================================
extern "C" void kernel_launch(void* const* d_in, const int* in_sizes, int n_in,
                              void* d_out, int out_size) {
    const int*   node_idx = (const int*)d_in[0];
    const int*   ei       = (const int*)d_in[1];
    const float* ew       = (const float*)d_in[2];
    const float* emb      = (const float*)d_in[3];
    const float* W1       = (const float*)d_in[4];
    const float* b1       = (const float*)d_in[5];
    const float* W2       = (const float*)d_in[6];
    const float* b2       = (const float*)d_in[7];
    const float* Wout     = (const float*)d_in[8];
    const float* bout     = (const float*)d_in[9];
    float* out = (float*)d_out;
    const int* row = ei;
    const int* col = ei + EE;

    constexpr int SMEM_L = 4 * A_CH_BYTES + 2 * B_CH_BYTES;   // 163840
    constexpr int SMEM_F = 2 * A_CH_BYTES + 2 * B_CH_BYTES;   //  98304
    cudaFuncSetAttribute((const void*)gemm_kernel<KE2, 4, KE2, KE2>,
                         cudaFuncAttributeMaxDynamicSharedMemorySize, SMEM_L);
    cudaFuncSetAttribute((const void*)gemm_kernel<128, 2, KE2, 128>,
                         cudaFuncAttributeMaxDynamicSharedMemorySize, SMEM_F);

    // preprocessing: CSC by destination + symmetric norm
    k_init<<<(NN + 255) / 256, 256>>>();
    k_hist<<<(EE + 255) / 256, 256>>>(row, col, ew);
    k_dinv<<<(NN + 255) / 256, 256>>>();
    k_scanA<<<NBLK_SCAN, 1024>>>();
    k_scanB<<<1, 1>>>();
    k_scanC<<<NBLK_SCAN, 1024>>>();
    k_fill<<<(EE + 255) / 256, 256>>>(row, col, ew);

    const int gemm_grid = MPAD / TM;                 // 391
    const int spmm_grid = (NN + 7) / 8;

    // layer 1: 2-term GEMM
    k_splitA1<<<4096, 256>>>(emb, node_idx);
    k_splitB<true><<<64, 256>>>(W1, FEAT);
    gemm_kernel<KE2, 4, KE2, KE2><<<gemm_grid, 512, SMEM_L>>>(
        nullptr, 0, FEAT, 1, MPAD, nullptr);
    k_spmm<true><<<spmm_grid, 256>>>(b1);

    // layer 2: 2-term GEMM; spmm writes hi only (final GEMM is 1-term)
    k_splitB<true><<<64, 256>>>(W2, FEAT);
    gemm_kernel<KE2, 4, KE2, KE2><<<gemm_grid, 512, SMEM_L>>>(
        nullptr, 0, FEAT, 1, MPAD, nullptr);
    k_spmm<false><<<spmm_grid, 256>>>(b2);

    // output layer: single-term fp16 (K=128), grid (391, 2), 8 n-iters each
    k_splitB<false><<<1024, 256>>>(Wout, NLAB);
    gemm_kernel<128, 2, KE2, 128><<<dim3(gemm_grid, 2), 512, SMEM_F>>>(
        out, 1, NLAB, 8, NN, bout);
}

// round 9
// speedup vs baseline: 1.7694x; 1.0938x over previous
#include <cuda_runtime.h>
#include <cuda_fp16.h>
#include <cstdint>

#define NN 100000
#define EE 1000000
#define FEAT 128
#define NLAB 2048
#define MPAD 100096            // 391 * 256
#define KE1 128                // single-term fp16: A=xhi, B=Whi
#define NBLK_SCAN 98

// GEMM tiling
#define TM 256
#define KCH 64
#define A_CH_BYTES (TM * 128)          // 32768
#define B_CH_BYTES (128 * 128)         // 16384

// ======================= device scratch =====================================
static __device__ __align__(16) __half g_Asplit[(size_t)MPAD * KE1]; // 25.6 MB
static __device__ __align__(16) __half g_Bsplit[(size_t)NLAB * KE1]; //  0.5 MB
static __device__ __align__(16) float g_H[(size_t)MPAD * FEAT];      // 51.2 MB
static __device__ float g_deg[NN];
static __device__ float g_dinv[NN];
static __device__ int   g_cnt[NN];
static __device__ int   g_colptr[NN];
static __device__ int   g_cursor[NN];
static __device__ int   g_bsum[128];
static __device__ int   g_bofs[128];
static __device__ int   g_esrc[EE];
static __device__ float g_eww[EE];

// ======================= helpers ============================================
__device__ __forceinline__ uint32_t smem_u32(const void* p) {
    uint32_t a;
    asm("{ .reg .u64 t; cvta.to.shared.u64 t, %1; cvt.u32.u64 %0, t; }" : "=r"(a) : "l"(p));
    return a;
}
#define SWZ128(x) ((x) ^ (((x) >> 3) & 0x70))

__device__ __forceinline__ void cpa16(uint32_t s, const void* g) {
    asm volatile("cp.async.cg.shared.global [%0], [%1], 16;"
                 :: "r"(s), "l"(__cvta_generic_to_global(g)) : "memory");
}
__device__ __forceinline__ void cpa_commit() {
    asm volatile("cp.async.commit_group;" ::: "memory");
}
__device__ __forceinline__ void cpa_wait1() {
    asm volatile("cp.async.wait_group 1;" ::: "memory");
}
__device__ __forceinline__ void ldmA4(uint32_t* r, uint32_t addr) {
    asm volatile("ldmatrix.sync.aligned.m8n8.x4.shared.b16 {%0,%1,%2,%3}, [%4];"
                 : "=r"(r[0]), "=r"(r[1]), "=r"(r[2]), "=r"(r[3]) : "r"(addr));
}
__device__ __forceinline__ void mma16816(float* d, const uint32_t* a, uint32_t b0, uint32_t b1) {
    asm volatile(
        "mma.sync.aligned.m16n8k16.row.col.f32.f16.f16.f32 "
        "{%0,%1,%2,%3}, {%4,%5,%6,%7}, {%8,%9}, {%0,%1,%2,%3};"
        : "+f"(d[0]), "+f"(d[1]), "+f"(d[2]), "+f"(d[3])
        : "r"(a[0]), "r"(a[1]), "r"(a[2]), "r"(a[3]), "r"(b0), "r"(b1));
}

// ======================= graph preprocessing ================================
__global__ void k_init() {
    int i = blockIdx.x * blockDim.x + threadIdx.x;
    if (i < NN) { g_deg[i] = 1.0f; g_cnt[i] = 0; }
}
__global__ void k_hist(const int* __restrict__ row, const int* __restrict__ col,
                       const float* __restrict__ ew) {
    int e = blockIdx.x * blockDim.x + threadIdx.x;
    if (e < EE) {
        int c = col[e];
        atomicAdd(&g_deg[c], ew[e]);
        atomicAdd(&g_cnt[c], 1);
    }
}
__global__ void k_dinv() {
    int i = blockIdx.x * blockDim.x + threadIdx.x;
    if (i < NN) g_dinv[i] = rsqrtf(g_deg[i]);
}
__global__ void k_scanA() {
    __shared__ int s[1024];
    int t = threadIdx.x;
    int i = blockIdx.x * 1024 + t;
    int v = (i < NN) ? g_cnt[i] : 0;
    s[t] = v;
    __syncthreads();
    for (int off = 1; off < 1024; off <<= 1) {
        int add = (t >= off) ? s[t - off] : 0;
        __syncthreads();
        s[t] += add;
        __syncthreads();
    }
    if (i < NN) g_colptr[i] = s[t] - v;
    if (t == 1023) g_bsum[blockIdx.x] = s[1023];
}
__global__ void k_scanB() {
    int acc = 0;
    for (int b = 0; b < NBLK_SCAN; b++) { g_bofs[b] = acc; acc += g_bsum[b]; }
}
__global__ void k_scanC() {
    int i = blockIdx.x * 1024 + threadIdx.x;
    if (i < NN) {
        int ex = g_colptr[i] + g_bofs[blockIdx.x];
        g_colptr[i] = ex;
        g_cursor[i] = ex;
    }
}
__global__ void k_fill(const int* __restrict__ row, const int* __restrict__ col,
                       const float* __restrict__ ew) {
    int e = blockIdx.x * blockDim.x + threadIdx.x;
    if (e < EE) {
        int c = col[e], r = row[e];
        int pos = atomicAdd(&g_cursor[c], 1);
        g_esrc[pos] = r;
        g_eww[pos] = g_dinv[r] * ew[e] * g_dinv[c];
    }
}

// ======================= splits (single-term) ================================
__global__ void k_splitA1(const float* __restrict__ emb, const int* __restrict__ idx) {
    const size_t total = (size_t)NN * FEAT;
    for (size_t i = (size_t)blockIdx.x * blockDim.x + threadIdx.x; i < total;
         i += (size_t)gridDim.x * blockDim.x) {
        int m = (int)(i >> 7), k = (int)(i & 127);
        float v = emb[(size_t)idx[m] * FEAT + k];
        g_Asplit[(size_t)m * KE1 + k] = __float2half(v);
    }
}
__global__ void k_splitB(const float* __restrict__ W, int ncols) {
    int total = ncols * FEAT;
    for (int i = blockIdx.x * blockDim.x + threadIdx.x; i < total;
         i += gridDim.x * blockDim.x) {
        int nr = i >> 7, k = i & 127;
        float v = W[(size_t)k * ncols + nr];
        g_Bsplit[(size_t)nr * KE1 + k] = __float2half(v);
    }
}

// ======================= mma.sync GEMM (R3-proven body) =====================
// C[m0:m0+256, cols] = A[m0:m0+256, 0:KE] @ B[:, 0:KE]^T, strides LDA/LDB.
// 512 threads = 16 warps (4m x 4n), warp tile 64x32, full-K A resident in SMEM,
// B streamed in 64-K chunks double-buffered with cp.async.
template <int KE, int NCH, int LDA, int LDB>
__global__ void __launch_bounds__(512, 1)
gemm_kernel(float* __restrict__ Cext, int dst_sel, int ldC, int nIters, int Mreal,
            const float* __restrict__ bias) {
    constexpr int B_OFF = NCH * A_CH_BYTES;
    extern __shared__ char smem[];
    uint32_t sb = smem_u32(smem);
    int tid = threadIdx.x, lid = tid & 31, wid = tid >> 5;
    int warp_m = wid >> 2, warp_n = wid & 3;
    int m0 = blockIdx.x * TM;
    int n0_base = blockIdx.y * nIters;      // units of 128-col tiles

    float* C = dst_sel ? Cext : g_H;
    const __half* Ag = g_Asplit + (size_t)m0 * LDA;

    // group 0: full A tile + B chunk 0 of first n-iter
    #pragma unroll
    for (int c = 0; c < NCH; c++) {
        for (int i = tid; i < TM * 8; i += 512) {
            int r = i >> 3, s = i & 7;
            cpa16(sb + c * A_CH_BYTES + SWZ128(r * 128 + s * 16),
                  Ag + (size_t)r * LDA + c * KCH + s * 8);
        }
    }
    {
        const __half* Bg = g_Bsplit + (size_t)(n0_base * 128) * LDB;
        for (int i = tid; i < 128 * 8; i += 512) {
            int r = i >> 3, s = i & 7;
            cpa16(sb + B_OFF + SWZ128(r * 128 + s * 16), Bg + (size_t)r * LDB + s * 8);
        }
    }
    cpa_commit();

    const int a_row = warp_m * 64 + (lid & 7) + ((lid >> 3) & 1) * 8;
    const int a_ks  = (lid >> 4) * 8;
    const int b_row = warp_n * 32 + (lid & 7) + ((lid >> 4) & 1) * 8;
    const int b_ks  = ((lid >> 3) & 1) * 8;

    for (int it = 0; it < nIters; it++) {
        float acc[4][4][4];
        #pragma unroll
        for (int mi = 0; mi < 4; mi++)
            #pragma unroll
            for (int nj = 0; nj < 4; nj++)
                #pragma unroll
                for (int q = 0; q < 4; q++) acc[mi][nj][q] = 0.0f;

        for (int c = 0; c < NCH; c++) {
            int buf = c & 1;                       // NCH even -> parity stable
            int nc = c + 1, nit = it;
            if (nc == NCH) { nc = 0; nit = it + 1; }
            if (nit < nIters) {
                const __half* Bg = g_Bsplit + (size_t)((n0_base + nit) * 128) * LDB + nc * KCH;
                uint32_t bb = sb + B_OFF + (buf ^ 1) * B_CH_BYTES;
                for (int i = tid; i < 128 * 8; i += 512) {
                    int r = i >> 3, s = i & 7;
                    cpa16(bb + SWZ128(r * 128 + s * 16), Bg + (size_t)r * LDB + s * 8);
                }
            }
            cpa_commit();
            cpa_wait1();
            __syncthreads();

            uint32_t Ab = sb + c * A_CH_BYTES;
            uint32_t Bb = sb + B_OFF + buf * B_CH_BYTES;
            #pragma unroll
            for (int ks = 0; ks < 4; ks++) {
                uint32_t a[4][4], b[2][4];
                #pragma unroll
                for (int mi = 0; mi < 4; mi++)
                    ldmA4(a[mi], Ab + SWZ128((a_row + mi * 16) * 128 + (a_ks + ks * 16) * 2));
                #pragma unroll
                for (int bi = 0; bi < 2; bi++)
                    ldmA4(b[bi], Bb + SWZ128((b_row + bi * 16) * 128 + (b_ks + ks * 16) * 2));
                #pragma unroll
                for (int mi = 0; mi < 4; mi++)
                    #pragma unroll
                    for (int nj = 0; nj < 4; nj++)
                        mma16816(acc[mi][nj], a[mi], b[nj >> 1][(nj & 1) * 2],
                                 b[nj >> 1][(nj & 1) * 2 + 1]);
            }
            __syncthreads();
        }

        int n0 = (n0_base + it) * 128;
        #pragma unroll
        for (int mi = 0; mi < 4; mi++) {
            int r0 = m0 + warp_m * 64 + mi * 16 + (lid >> 2);
            #pragma unroll
            for (int nj = 0; nj < 4; nj++) {
                int col = n0 + warp_n * 32 + nj * 8 + ((lid & 3) << 1);
                float bx = bias ? bias[col] : 0.0f;
                float by = bias ? bias[col + 1] : 0.0f;
                if (r0 < Mreal) {
                    float2 o = {acc[mi][nj][0] + bx, acc[mi][nj][1] + by};
                    *(float2*)(C + (size_t)r0 * ldC + col) = o;
                }
                if (r0 + 8 < Mreal) {
                    float2 o = {acc[mi][nj][2] + bx, acc[mi][nj][3] + by};
                    *(float2*)(C + (size_t)(r0 + 8) * ldC + col) = o;
                }
            }
        }
    }
}

// ======================= SpMM + fused fp16 cast =============================
// X[dst] = relu( dinv^2 * H[dst] + sum w_e H[src] + bias ); write hi into
// g_Asplit at stride 128.
__global__ void k_spmm(const float* __restrict__ bias) {
    int gw = (blockIdx.x * blockDim.x + threadIdx.x) >> 5;
    int lane = threadIdx.x & 31;
    if (gw >= NN) return;
    const float4* H4 = (const float4*)g_H;
    float di = g_dinv[gw];
    float s = di * di;
    float4 acc = H4[(size_t)gw * 32 + lane];
    acc.x *= s; acc.y *= s; acc.z *= s; acc.w *= s;
    int start = g_colptr[gw];
    int len = g_cnt[gw];
    int j = 0;
    for (; j + 2 <= len; j += 2) {
        int e0 = start + j, e1 = e0 + 1;
        int s0 = g_esrc[e0], s1 = g_esrc[e1];
        float w0 = g_eww[e0], w1 = g_eww[e1];
        float4 v0 = H4[(size_t)s0 * 32 + lane];
        float4 v1 = H4[(size_t)s1 * 32 + lane];
        acc.x += w0 * v0.x + w1 * v1.x;
        acc.y += w0 * v0.y + w1 * v1.y;
        acc.z += w0 * v0.z + w1 * v1.z;
        acc.w += w0 * v0.w + w1 * v1.w;
    }
    if (j < len) {
        int e = start + j;
        int src = g_esrc[e];
        float w = g_eww[e];
        float4 v = H4[(size_t)src * 32 + lane];
        acc.x += w * v.x; acc.y += w * v.y; acc.z += w * v.z; acc.w += w * v.w;
    }
    float4 b4 = ((const float4*)bias)[lane];
    acc.x = fmaxf(acc.x + b4.x, 0.0f);
    acc.y = fmaxf(acc.y + b4.y, 0.0f);
    acc.z = fmaxf(acc.z + b4.z, 0.0f);
    acc.w = fmaxf(acc.w + b4.w, 0.0f);

    __half2 hp0 = __halves2half2(__float2half(acc.x), __float2half(acc.y));
    __half2 hp1 = __halves2half2(__float2half(acc.z), __float2half(acc.w));
    uint2 hv = {*(uint32_t*)&hp0, *(uint32_t*)&hp1};
    *(uint2*)(g_Asplit + (size_t)gw * KE1 + lane * 4) = hv;
}

// ======================= launch =============================================
extern "C" void kernel_launch(void* const* d_in, const int* in_sizes, int n_in,
                              void* d_out, int out_size) {
    const int*   node_idx = (const int*)d_in[0];
    const int*   ei       = (const int*)d_in[1];
    const float* ew       = (const float*)d_in[2];
    const float* emb      = (const float*)d_in[3];
    const float* W1       = (const float*)d_in[4];
    const float* b1       = (const float*)d_in[5];
    const float* W2       = (const float*)d_in[6];
    const float* b2       = (const float*)d_in[7];
    const float* Wout     = (const float*)d_in[8];
    const float* bout     = (const float*)d_in[9];
    float* out = (float*)d_out;
    const int* row = ei;
    const int* col = ei + EE;

    constexpr int SMEM_F = 2 * A_CH_BYTES + 2 * B_CH_BYTES;   // 98304
    cudaFuncSetAttribute((const void*)gemm_kernel<KE1, 2, KE1, KE1>,
                         cudaFuncAttributeMaxDynamicSharedMemorySize, SMEM_F);

    // preprocessing: CSC by destination + symmetric norm
    k_init<<<(NN + 255) / 256, 256>>>();
    k_hist<<<(EE + 255) / 256, 256>>>(row, col, ew);
    k_dinv<<<(NN + 255) / 256, 256>>>();
    k_scanA<<<NBLK_SCAN, 1024>>>();
    k_scanB<<<1, 1>>>();
    k_scanC<<<NBLK_SCAN, 1024>>>();
    k_fill<<<(EE + 255) / 256, 256>>>(row, col, ew);

    const int gemm_grid = MPAD / TM;                 // 391
    const int spmm_grid = (NN + 7) / 8;

    // layer 1
    k_splitA1<<<4096, 256>>>(emb, node_idx);
    k_splitB<<<64, 256>>>(W1, FEAT);
    gemm_kernel<KE1, 2, KE1, KE1><<<gemm_grid, 512, SMEM_F>>>(
        nullptr, 0, FEAT, 1, MPAD, nullptr);
    k_spmm<<<spmm_grid, 256>>>(b1);

    // layer 2
    k_splitB<<<64, 256>>>(W2, FEAT);
    gemm_kernel<KE1, 2, KE1, KE1><<<gemm_grid, 512, SMEM_F>>>(
        nullptr, 0, FEAT, 1, MPAD, nullptr);
    k_spmm<<<spmm_grid, 256>>>(b2);

    // output layer: grid (391, 4), 4 n-iters each
    k_splitB<<<1024, 256>>>(Wout, NLAB);
    gemm_kernel<KE1, 2, KE1, KE1><<<dim3(gemm_grid, 4), 512, SMEM_F>>>(
        out, 1, NLAB, 4, NN, bout);
}

// round 10
// speedup vs baseline: 1.9609x; 1.1082x over previous
#include <cuda_runtime.h>
#include <cuda_fp16.h>
#include <cstdint>

#define NN 100000
#define EE 1000000
#define FEAT 128
#define NLAB 2048
#define MPAD 100096            // 391 * 256
#define KE1 128                // single-term fp16: A=xhi, B=Whi
#define NBLK_SCAN 98

// GEMM tiling
#define TM 256
#define KCH 64
#define A_CH_BYTES (TM * 128)          // 32768
#define B_CH_BYTES (128 * 128)         // 16384

// ======================= device scratch =====================================
static __device__ __align__(16) __half g_Asplit[(size_t)MPAD * KE1]; // 25.6 MB
static __device__ __align__(16) __half g_Bsplit[(size_t)NLAB * KE1]; //  0.5 MB
static __device__ __align__(16) __half g_Hh[(size_t)MPAD * FEAT];    // 25.6 MB
static __device__ float g_deg[NN];
static __device__ float g_dinv[NN];
static __device__ int   g_cnt[NN];
static __device__ int   g_colptr[NN];
static __device__ int   g_cursor[NN];
static __device__ int   g_bsum[128];
static __device__ int   g_bofs[128];
static __device__ int   g_esrc[EE];
static __device__ float g_eww[EE];

// ======================= helpers ============================================
__device__ __forceinline__ uint32_t smem_u32(const void* p) {
    uint32_t a;
    asm("{ .reg .u64 t; cvta.to.shared.u64 t, %1; cvt.u32.u64 %0, t; }" : "=r"(a) : "l"(p));
    return a;
}
#define SWZ128(x) ((x) ^ (((x) >> 3) & 0x70))

__device__ __forceinline__ void cpa16(uint32_t s, const void* g) {
    asm volatile("cp.async.cg.shared.global [%0], [%1], 16;"
                 :: "r"(s), "l"(__cvta_generic_to_global(g)) : "memory");
}
__device__ __forceinline__ void cpa_commit() {
    asm volatile("cp.async.commit_group;" ::: "memory");
}
__device__ __forceinline__ void cpa_wait1() {
    asm volatile("cp.async.wait_group 1;" ::: "memory");
}
__device__ __forceinline__ void ldmA4(uint32_t* r, uint32_t addr) {
    asm volatile("ldmatrix.sync.aligned.m8n8.x4.shared.b16 {%0,%1,%2,%3}, [%4];"
                 : "=r"(r[0]), "=r"(r[1]), "=r"(r[2]), "=r"(r[3]) : "r"(addr));
}
__device__ __forceinline__ void mma16816(float* d, const uint32_t* a, uint32_t b0, uint32_t b1) {
    asm volatile(
        "mma.sync.aligned.m16n8k16.row.col.f32.f16.f16.f32 "
        "{%0,%1,%2,%3}, {%4,%5,%6,%7}, {%8,%9}, {%0,%1,%2,%3};"
        : "+f"(d[0]), "+f"(d[1]), "+f"(d[2]), "+f"(d[3])
        : "r"(a[0]), "r"(a[1]), "r"(a[2]), "r"(a[3]), "r"(b0), "r"(b1));
}

// ======================= graph preprocessing ================================
__global__ void k_init() {
    int i = blockIdx.x * blockDim.x + threadIdx.x;
    if (i < NN) { g_deg[i] = 1.0f; g_cnt[i] = 0; }
}
__global__ void k_hist(const int* __restrict__ row, const int* __restrict__ col,
                       const float* __restrict__ ew) {
    int e = blockIdx.x * blockDim.x + threadIdx.x;
    if (e < EE) {
        int c = col[e];
        atomicAdd(&g_deg[c], ew[e]);
        atomicAdd(&g_cnt[c], 1);
    }
}
__global__ void k_scanA() {
    __shared__ int s[1024];
    int t = threadIdx.x;
    int i = blockIdx.x * 1024 + t;
    int v = (i < NN) ? g_cnt[i] : 0;
    s[t] = v;
    __syncthreads();
    for (int off = 1; off < 1024; off <<= 1) {
        int add = (t >= off) ? s[t - off] : 0;
        __syncthreads();
        s[t] += add;
        __syncthreads();
    }
    if (i < NN) g_colptr[i] = s[t] - v;
    if (t == 1023) g_bsum[blockIdx.x] = s[1023];
}
__global__ void k_scanB() {
    int acc = 0;
    for (int b = 0; b < NBLK_SCAN; b++) { g_bofs[b] = acc; acc += g_bsum[b]; }
}
// scanC + dinv merged (both depend only on hist/scanA/scanB)
__global__ void k_scanC() {
    int i = blockIdx.x * 1024 + threadIdx.x;
    if (i < NN) {
        int ex = g_colptr[i] + g_bofs[blockIdx.x];
        g_colptr[i] = ex;
        g_cursor[i] = ex;
        g_dinv[i] = rsqrtf(g_deg[i]);
    }
}
__global__ void k_fill(const int* __restrict__ row, const int* __restrict__ col,
                       const float* __restrict__ ew) {
    int e = blockIdx.x * blockDim.x + threadIdx.x;
    if (e < EE) {
        int c = col[e], r = row[e];
        int pos = atomicAdd(&g_cursor[c], 1);
        g_esrc[pos] = r;
        g_eww[pos] = g_dinv[r] * ew[e] * g_dinv[c];
    }
}

// ======================= splits (single-term) ================================
__global__ void k_splitA1(const float* __restrict__ emb, const int* __restrict__ idx) {
    const size_t total = (size_t)NN * FEAT;
    for (size_t i = (size_t)blockIdx.x * blockDim.x + threadIdx.x; i < total;
         i += (size_t)gridDim.x * blockDim.x) {
        int m = (int)(i >> 7), k = (int)(i & 127);
        float v = emb[(size_t)idx[m] * FEAT + k];
        g_Asplit[(size_t)m * KE1 + k] = __float2half(v);
    }
}
__global__ void k_splitB(const float* __restrict__ W, int ncols) {
    int total = ncols * FEAT;
    for (int i = blockIdx.x * blockDim.x + threadIdx.x; i < total;
         i += gridDim.x * blockDim.x) {
        int nr = i >> 7, k = i & 127;
        float v = W[(size_t)k * ncols + nr];
        g_Bsplit[(size_t)nr * KE1 + k] = __float2half(v);
    }
}

// ======================= mma.sync GEMM (R3-proven body) =====================
// C = A[m0:m0+256, 0:KE] @ B[:, 0:KE]^T. HALF_OUT: write fp16 to g_Hh (no
// bias); else fp32 to Cext (+bias). 512 threads = 16 warps (4m x 4n), warp
// tile 64x32, full-K A in SMEM, B double-buffered via cp.async.
template <int KE, int NCH, int LDA, int LDB, bool HALF_OUT>
__global__ void __launch_bounds__(512, 1)
gemm_kernel(float* __restrict__ Cext, int ldC, int nIters, int Mreal,
            const float* __restrict__ bias) {
    constexpr int B_OFF = NCH * A_CH_BYTES;
    extern __shared__ char smem[];
    uint32_t sb = smem_u32(smem);
    int tid = threadIdx.x, lid = tid & 31, wid = tid >> 5;
    int warp_m = wid >> 2, warp_n = wid & 3;
    int m0 = blockIdx.x * TM;
    int n0_base = blockIdx.y * nIters;      // units of 128-col tiles

    const __half* Ag = g_Asplit + (size_t)m0 * LDA;

    // group 0: full A tile + B chunk 0 of first n-iter
    #pragma unroll
    for (int c = 0; c < NCH; c++) {
        for (int i = tid; i < TM * 8; i += 512) {
            int r = i >> 3, s = i & 7;
            cpa16(sb + c * A_CH_BYTES + SWZ128(r * 128 + s * 16),
                  Ag + (size_t)r * LDA + c * KCH + s * 8);
        }
    }
    {
        const __half* Bg = g_Bsplit + (size_t)(n0_base * 128) * LDB;
        for (int i = tid; i < 128 * 8; i += 512) {
            int r = i >> 3, s = i & 7;
            cpa16(sb + B_OFF + SWZ128(r * 128 + s * 16), Bg + (size_t)r * LDB + s * 8);
        }
    }
    cpa_commit();

    const int a_row = warp_m * 64 + (lid & 7) + ((lid >> 3) & 1) * 8;
    const int a_ks  = (lid >> 4) * 8;
    const int b_row = warp_n * 32 + (lid & 7) + ((lid >> 4) & 1) * 8;
    const int b_ks  = ((lid >> 3) & 1) * 8;

    for (int it = 0; it < nIters; it++) {
        float acc[4][4][4];
        #pragma unroll
        for (int mi = 0; mi < 4; mi++)
            #pragma unroll
            for (int nj = 0; nj < 4; nj++)
                #pragma unroll
                for (int q = 0; q < 4; q++) acc[mi][nj][q] = 0.0f;

        for (int c = 0; c < NCH; c++) {
            int buf = c & 1;                       // NCH even -> parity stable
            int nc = c + 1, nit = it;
            if (nc == NCH) { nc = 0; nit = it + 1; }
            if (nit < nIters) {
                const __half* Bg = g_Bsplit + (size_t)((n0_base + nit) * 128) * LDB + nc * KCH;
                uint32_t bb = sb + B_OFF + (buf ^ 1) * B_CH_BYTES;
                for (int i = tid; i < 128 * 8; i += 512) {
                    int r = i >> 3, s = i & 7;
                    cpa16(bb + SWZ128(r * 128 + s * 16), Bg + (size_t)r * LDB + s * 8);
                }
            }
            cpa_commit();
            cpa_wait1();
            __syncthreads();

            uint32_t Ab = sb + c * A_CH_BYTES;
            uint32_t Bb = sb + B_OFF + buf * B_CH_BYTES;
            #pragma unroll
            for (int ks = 0; ks < 4; ks++) {
                uint32_t a[4][4], b[2][4];
                #pragma unroll
                for (int mi = 0; mi < 4; mi++)
                    ldmA4(a[mi], Ab + SWZ128((a_row + mi * 16) * 128 + (a_ks + ks * 16) * 2));
                #pragma unroll
                for (int bi = 0; bi < 2; bi++)
                    ldmA4(b[bi], Bb + SWZ128((b_row + bi * 16) * 128 + (b_ks + ks * 16) * 2));
                #pragma unroll
                for (int mi = 0; mi < 4; mi++)
                    #pragma unroll
                    for (int nj = 0; nj < 4; nj++)
                        mma16816(acc[mi][nj], a[mi], b[nj >> 1][(nj & 1) * 2],
                                 b[nj >> 1][(nj & 1) * 2 + 1]);
            }
            __syncthreads();
        }

        int n0 = (n0_base + it) * 128;
        #pragma unroll
        for (int mi = 0; mi < 4; mi++) {
            int r0 = m0 + warp_m * 64 + mi * 16 + (lid >> 2);
            #pragma unroll
            for (int nj = 0; nj < 4; nj++) {
                int col = n0 + warp_n * 32 + nj * 8 + ((lid & 3) << 1);
                if (HALF_OUT) {
                    if (r0 < Mreal) {
                        __half2 h = __floats2half2_rn(acc[mi][nj][0], acc[mi][nj][1]);
                        *(__half2*)(g_Hh + (size_t)r0 * FEAT + col) = h;
                    }
                    if (r0 + 8 < Mreal) {
                        __half2 h = __floats2half2_rn(acc[mi][nj][2], acc[mi][nj][3]);
                        *(__half2*)(g_Hh + (size_t)(r0 + 8) * FEAT + col) = h;
                    }
                } else {
                    float bx = bias[col];
                    float by = bias[col + 1];
                    if (r0 < Mreal) {
                        float2 o = {acc[mi][nj][0] + bx, acc[mi][nj][1] + by};
                        *(float2*)(Cext + (size_t)r0 * ldC + col) = o;
                    }
                    if (r0 + 8 < Mreal) {
                        float2 o = {acc[mi][nj][2] + bx, acc[mi][nj][3] + by};
                        *(float2*)(Cext + (size_t)(r0 + 8) * ldC + col) = o;
                    }
                }
            }
        }
    }
}

// ======================= SpMM over fp16 H + fused fp16 cast =================
// X[dst] = relu( dinv^2 * H[dst] + sum w_e H[src] + bias ); fp32 accumulate,
// write fp16 into g_Asplit at stride 128.
__device__ __forceinline__ void h4_fma(float4& acc, uint2 v, float w) {
    __half2 lo = *(__half2*)&v.x, hi = *(__half2*)&v.y;
    float2 f0 = __half22float2(lo), f1 = __half22float2(hi);
    acc.x += w * f0.x; acc.y += w * f0.y;
    acc.z += w * f1.x; acc.w += w * f1.y;
}
__global__ void k_spmm(const float* __restrict__ bias) {
    int gw = (blockIdx.x * blockDim.x + threadIdx.x) >> 5;
    int lane = threadIdx.x & 31;
    if (gw >= NN) return;
    const uint2* H2 = (const uint2*)g_Hh;    // 32 x uint2 per row (128 halves)
    float di = g_dinv[gw];
    float s = di * di;
    float4 acc = {0.f, 0.f, 0.f, 0.f};
    h4_fma(acc, H2[(size_t)gw * 32 + lane], s);
    int start = g_colptr[gw];
    int len = g_cnt[gw];
    int j = 0;
    for (; j + 4 <= len; j += 4) {
        int e = start + j;
        int s0 = g_esrc[e], s1 = g_esrc[e + 1], s2 = g_esrc[e + 2], s3 = g_esrc[e + 3];
        float w0 = g_eww[e], w1 = g_eww[e + 1], w2 = g_eww[e + 2], w3 = g_eww[e + 3];
        uint2 v0 = H2[(size_t)s0 * 32 + lane];
        uint2 v1 = H2[(size_t)s1 * 32 + lane];
        uint2 v2 = H2[(size_t)s2 * 32 + lane];
        uint2 v3 = H2[(size_t)s3 * 32 + lane];
        h4_fma(acc, v0, w0); h4_fma(acc, v1, w1);
        h4_fma(acc, v2, w2); h4_fma(acc, v3, w3);
    }
    for (; j < len; j++) {
        int e = start + j;
        h4_fma(acc, H2[(size_t)g_esrc[e] * 32 + lane], g_eww[e]);
    }
    float4 b4 = ((const float4*)bias)[lane];
    acc.x = fmaxf(acc.x + b4.x, 0.0f);
    acc.y = fmaxf(acc.y + b4.y, 0.0f);
    acc.z = fmaxf(acc.z + b4.z, 0.0f);
    acc.w = fmaxf(acc.w + b4.w, 0.0f);

    __half2 hp0 = __floats2half2_rn(acc.x, acc.y);
    __half2 hp1 = __floats2half2_rn(acc.z, acc.w);
    uint2 hv = {*(uint32_t*)&hp0, *(uint32_t*)&hp1};
    *(uint2*)(g_Asplit + (size_t)gw * KE1 + lane * 4) = hv;
}

// ======================= launch =============================================
extern "C" void kernel_launch(void* const* d_in, const int* in_sizes, int n_in,
                              void* d_out, int out_size) {
    const int*   node_idx = (const int*)d_in[0];
    const int*   ei       = (const int*)d_in[1];
    const float* ew       = (const float*)d_in[2];
    const float* emb      = (const float*)d_in[3];
    const float* W1       = (const float*)d_in[4];
    const float* b1       = (const float*)d_in[5];
    const float* W2       = (const float*)d_in[6];
    const float* b2       = (const float*)d_in[7];
    const float* Wout     = (const float*)d_in[8];
    const float* bout     = (const float*)d_in[9];
    float* out = (float*)d_out;
    const int* row = ei;
    const int* col = ei + EE;

    constexpr int SMEM_F = 2 * A_CH_BYTES + 2 * B_CH_BYTES;   // 98304
    cudaFuncSetAttribute((const void*)gemm_kernel<KE1, 2, KE1, KE1, true>,
                         cudaFuncAttributeMaxDynamicSharedMemorySize, SMEM_F);
    cudaFuncSetAttribute((const void*)gemm_kernel<KE1, 2, KE1, KE1, false>,
                         cudaFuncAttributeMaxDynamicSharedMemorySize, SMEM_F);

    // preprocessing: CSC by destination + symmetric norm
    k_init<<<(NN + 255) / 256, 256>>>();
    k_hist<<<(EE + 255) / 256, 256>>>(row, col, ew);
    k_scanA<<<NBLK_SCAN, 1024>>>();
    k_scanB<<<1, 1>>>();
    k_scanC<<<NBLK_SCAN, 1024>>>();
    k_fill<<<(EE + 255) / 256, 256>>>(row, col, ew);

    const int gemm_grid = MPAD / TM;                 // 391
    const int spmm_grid = (NN + 7) / 8;

    // layer 1
    k_splitA1<<<4096, 256>>>(emb, node_idx);
    k_splitB<<<64, 256>>>(W1, FEAT);
    gemm_kernel<KE1, 2, KE1, KE1, true><<<gemm_grid, 512, SMEM_F>>>(
        nullptr, FEAT, 1, MPAD, nullptr);
    k_spmm<<<spmm_grid, 256>>>(b1);

    // layer 2
    k_splitB<<<64, 256>>>(W2, FEAT);
    gemm_kernel<KE1, 2, KE1, KE1, true><<<gemm_grid, 512, SMEM_F>>>(
        nullptr, FEAT, 1, MPAD, nullptr);
    k_spmm<<<spmm_grid, 256>>>(b2);

    // output layer: grid (391, 4), 4 n-iters each, fp32 out + bias
    k_splitB<<<1024, 256>>>(Wout, NLAB);
    gemm_kernel<KE1, 2, KE1, KE1, false><<<dim3(gemm_grid, 4), 512, SMEM_F>>>(
        out, NLAB, 4, NN, bout);
}

// round 12
// speedup vs baseline: 2.0314x; 1.0359x over previous
#include <cuda_runtime.h>
#include <cuda_fp16.h>
#include <cstdint>

#define NN 100000
#define EE 1000000
#define FEAT 128
#define NLAB 2048
#define MPAD 100096            // 391 * 256
#define KE1 128                // single-term fp16: A=xhi, B=Whi
#define NBLK_SCAN 98

// GEMM tiling
#define TM 256
#define KCH 64
#define A_CH_BYTES (TM * 128)          // 32768
#define B_CH_BYTES (128 * 128)         // 16384

typedef unsigned long long ull;

// ======================= device scratch =====================================
static __device__ __align__(16) __half g_Asplit[(size_t)MPAD * KE1];   // 25.6 MB
static __device__ __align__(16) __half g_Bsplit1[FEAT * KE1];          // 32 KB
static __device__ __align__(16) __half g_Bsplit2[FEAT * KE1];          // 32 KB
static __device__ __align__(16) __half g_BsplitO[NLAB * KE1];          // 512 KB
static __device__ __align__(16) __half g_Hh[(size_t)MPAD * FEAT];      // 25.6 MB
static __device__ ull   g_packed[NN];      // count<<42 | sum(ew)*2^32
static __device__ float g_dinv[NN];
static __device__ int   g_cnt[NN];
static __device__ int   g_colptr[NN];
static __device__ int   g_cursor[NN];
static __device__ int   g_bsum[128];
static __device__ int   g_bofs[128];
static __device__ int   g_esrc[EE];
static __device__ float g_eww[EE];

// ======================= helpers ============================================
__device__ __forceinline__ uint32_t smem_u32(const void* p) {
    uint32_t a;
    asm("{ .reg .u64 t; cvta.to.shared.u64 t, %1; cvt.u32.u64 %0, t; }" : "=r"(a) : "l"(p));
    return a;
}
#define SWZ128(x) ((x) ^ (((x) >> 3) & 0x70))

__device__ __forceinline__ void cpa16(uint32_t s, const void* g) {
    asm volatile("cp.async.cg.shared.global [%0], [%1], 16;"
                 :: "r"(s), "l"(__cvta_generic_to_global(g)) : "memory");
}
__device__ __forceinline__ void cpa_commit() {
    asm volatile("cp.async.commit_group;" ::: "memory");
}
__device__ __forceinline__ void cpa_wait1() {
    asm volatile("cp.async.wait_group 1;" ::: "memory");
}
__device__ __forceinline__ void ldmA4(uint32_t* r, uint32_t addr) {
    asm volatile("ldmatrix.sync.aligned.m8n8.x4.shared.b16 {%0,%1,%2,%3}, [%4];"
                 : "=r"(r[0]), "=r"(r[1]), "=r"(r[2]), "=r"(r[3]) : "r"(addr));
}
__device__ __forceinline__ void mma16816(float* d, const uint32_t* a, uint32_t b0, uint32_t b1) {
    asm volatile(
        "mma.sync.aligned.m16n8k16.row.col.f32.f16.f16.f32 "
        "{%0,%1,%2,%3}, {%4,%5,%6,%7}, {%8,%9}, {%0,%1,%2,%3};"
        : "+f"(d[0]), "+f"(d[1]), "+f"(d[2]), "+f"(d[3])
        : "r"(a[0]), "r"(a[1]), "r"(a[2]), "r"(a[3]), "r"(b0), "r"(b1));
}

// ======================= graph preprocessing ================================
__global__ void k_init() {
    int i = blockIdx.x * blockDim.x + threadIdx.x;
    if (i < NN) g_packed[i] = 0ULL;
}
// single 64-bit atomic per edge: count in [42:64), sum(ew)*2^32 in [0:42)
__global__ void k_hist(const int* __restrict__ col, const float* __restrict__ ew) {
    int e = blockIdx.x * blockDim.x + threadIdx.x;
    if (e < EE) {
        ull p = (1ULL << 42) | (ull)(ew[e] * 4294967296.0f);
        atomicAdd(&g_packed[col[e]], p);
    }
}
__global__ void k_scanA() {
    __shared__ int s[1024];
    int t = threadIdx.x;
    int i = blockIdx.x * 1024 + t;
    int v = (i < NN) ? (int)(g_packed[i] >> 42) : 0;
    s[t] = v;
    __syncthreads();
    for (int off = 1; off < 1024; off <<= 1) {
        int add = (t >= off) ? s[t - off] : 0;
        __syncthreads();
        s[t] += add;
        __syncthreads();
    }
    if (i < NN) g_colptr[i] = s[t] - v;
    if (t == 1023) g_bsum[blockIdx.x] = s[1023];
}
__global__ void k_scanB() {   // 1 block, 128 threads
    __shared__ int s[128];
    int t = threadIdx.x;
    int v = (t < NBLK_SCAN) ? g_bsum[t] : 0;
    s[t] = v;
    __syncthreads();
    for (int off = 1; off < 128; off <<= 1) {
        int add = (t >= off) ? s[t - off] : 0;
        __syncthreads();
        s[t] += add;
        __syncthreads();
    }
    if (t < NBLK_SCAN) g_bofs[t] = s[t] - v;
}
// finalize: colptr, cursor, cnt, dinv from packed
__global__ void k_scanC() {
    int i = blockIdx.x * 1024 + threadIdx.x;
    if (i < NN) {
        ull p = g_packed[i];
        int cnt = (int)(p >> 42);
        float wsum = (float)((double)(p & ((1ULL << 42) - 1)) * (1.0 / 4294967296.0));
        int ex = g_colptr[i] + g_bofs[blockIdx.x];
        g_colptr[i] = ex;
        g_cursor[i] = ex;
        g_cnt[i] = cnt;
        g_dinv[i] = rsqrtf(1.0f + wsum);
    }
}
__global__ void k_fill(const int* __restrict__ row, const int* __restrict__ col,
                       const float* __restrict__ ew) {
    int e = blockIdx.x * blockDim.x + threadIdx.x;
    if (e < EE) {
        int c = col[e], r = row[e];
        int pos = atomicAdd(&g_cursor[c], 1);
        g_esrc[pos] = r;
        g_eww[pos] = g_dinv[r] * ew[e] * g_dinv[c];
    }
}

// ======================= splits (single-term) ================================
__global__ void k_splitA1(const float* __restrict__ emb, const int* __restrict__ idx) {
    const size_t total = (size_t)NN * FEAT;
    for (size_t i = (size_t)blockIdx.x * blockDim.x + threadIdx.x; i < total;
         i += (size_t)gridDim.x * blockDim.x) {
        int m = (int)(i >> 7), k = (int)(i & 127);
        float v = emb[(size_t)idx[m] * FEAT + k];
        g_Asplit[(size_t)m * KE1 + k] = __float2half(v);
    }
}
// all three weight conversions in one launch
__global__ void k_splitBall(const float* __restrict__ W1, const float* __restrict__ W2,
                            const float* __restrict__ Wout) {
    int i = blockIdx.x * blockDim.x + threadIdx.x;
    if (i < FEAT * FEAT) {
        int nr = i >> 7, k = i & 127;
        g_Bsplit1[nr * 128 + k] = __float2half(W1[k * FEAT + nr]);
    } else if (i < 2 * FEAT * FEAT) {
        int j = i - FEAT * FEAT;
        int nr = j >> 7, k = j & 127;
        g_Bsplit2[nr * 128 + k] = __float2half(W2[k * FEAT + nr]);
    } else {
        int j = i - 2 * FEAT * FEAT;
        if (j < NLAB * FEAT) {
            int nr = j >> 7, k = j & 127;
            g_BsplitO[nr * 128 + k] = __float2half(Wout[(size_t)k * NLAB + nr]);
        }
    }
}

// compile-time B-buffer selection: keeps B addressing on a static global
// symbol (immediate base) exactly like the proven R10 codegen — a runtime
// pointer parameter here caused register spill (R11 failure).
template <int BSEL>
__device__ __forceinline__ const __half* bsel_ptr() {
    if (BSEL == 0) return g_Bsplit1;
    if (BSEL == 1) return g_Bsplit2;
    return g_BsplitO;
}

// ======================= mma.sync GEMM (R10-proven body) ====================
// C = A[m0:m0+256, 0:KE] @ B[:, 0:KE]^T. HALF_OUT: write fp16 to g_Hh (no
// bias); else fp32 to Cext (+bias). 512 threads = 16 warps (4m x 4n), warp
// tile 64x32, full-K A in SMEM, B double-buffered via cp.async.
template <int KE, int NCH, int LDA, int LDB, bool HALF_OUT, int BSEL>
__global__ void __launch_bounds__(512, 1)
gemm_kernel(float* __restrict__ Cext, int ldC, int nIters, int Mreal,
            const float* __restrict__ bias) {
    constexpr int B_OFF = NCH * A_CH_BYTES;
    extern __shared__ char smem[];
    uint32_t sb = smem_u32(smem);
    int tid = threadIdx.x, lid = tid & 31, wid = tid >> 5;
    int warp_m = wid >> 2, warp_n = wid & 3;
    int m0 = blockIdx.x * TM;
    int n0_base = blockIdx.y * nIters;      // units of 128-col tiles

    const __half* Ag = g_Asplit + (size_t)m0 * LDA;

    // group 0: full A tile + B chunk 0 of first n-iter
    #pragma unroll
    for (int c = 0; c < NCH; c++) {
        for (int i = tid; i < TM * 8; i += 512) {
            int r = i >> 3, s = i & 7;
            cpa16(sb + c * A_CH_BYTES + SWZ128(r * 128 + s * 16),
                  Ag + (size_t)r * LDA + c * KCH + s * 8);
        }
    }
    {
        const __half* Bg = bsel_ptr<BSEL>() + (size_t)(n0_base * 128) * LDB;
        for (int i = tid; i < 128 * 8; i += 512) {
            int r = i >> 3, s = i & 7;
            cpa16(sb + B_OFF + SWZ128(r * 128 + s * 16), Bg + (size_t)r * LDB + s * 8);
        }
    }
    cpa_commit();

    const int a_row = warp_m * 64 + (lid & 7) + ((lid >> 3) & 1) * 8;
    const int a_ks  = (lid >> 4) * 8;
    const int b_row = warp_n * 32 + (lid & 7) + ((lid >> 4) & 1) * 8;
    const int b_ks  = ((lid >> 3) & 1) * 8;

    for (int it = 0; it < nIters; it++) {
        float acc[4][4][4];
        #pragma unroll
        for (int mi = 0; mi < 4; mi++)
            #pragma unroll
            for (int nj = 0; nj < 4; nj++)
                #pragma unroll
                for (int q = 0; q < 4; q++) acc[mi][nj][q] = 0.0f;

        for (int c = 0; c < NCH; c++) {
            int buf = c & 1;                       // NCH even -> parity stable
            int nc = c + 1, nit = it;
            if (nc == NCH) { nc = 0; nit = it + 1; }
            if (nit < nIters) {
                const __half* Bg = bsel_ptr<BSEL>() +
                                   (size_t)((n0_base + nit) * 128) * LDB + nc * KCH;
                uint32_t bb = sb + B_OFF + (buf ^ 1) * B_CH_BYTES;
                for (int i = tid; i < 128 * 8; i += 512) {
                    int r = i >> 3, s = i & 7;
                    cpa16(bb + SWZ128(r * 128 + s * 16), Bg + (size_t)r * LDB + s * 8);
                }
            }
            cpa_commit();
            cpa_wait1();
            __syncthreads();

            uint32_t Ab = sb + c * A_CH_BYTES;
            uint32_t Bb = sb + B_OFF + buf * B_CH_BYTES;
            #pragma unroll
            for (int ks = 0; ks < 4; ks++) {
                uint32_t a[4][4], b[2][4];
                #pragma unroll
                for (int mi = 0; mi < 4; mi++)
                    ldmA4(a[mi], Ab + SWZ128((a_row + mi * 16) * 128 + (a_ks + ks * 16) * 2));
                #pragma unroll
                for (int bi = 0; bi < 2; bi++)
                    ldmA4(b[bi], Bb + SWZ128((b_row + bi * 16) * 128 + (b_ks + ks * 16) * 2));
                #pragma unroll
                for (int mi = 0; mi < 4; mi++)
                    #pragma unroll
                    for (int nj = 0; nj < 4; nj++)
                        mma16816(acc[mi][nj], a[mi], b[nj >> 1][(nj & 1) * 2],
                                 b[nj >> 1][(nj & 1) * 2 + 1]);
            }
            __syncthreads();
        }

        int n0 = (n0_base + it) * 128;
        #pragma unroll
        for (int mi = 0; mi < 4; mi++) {
            int r0 = m0 + warp_m * 64 + mi * 16 + (lid >> 2);
            #pragma unroll
            for (int nj = 0; nj < 4; nj++) {
                int col = n0 + warp_n * 32 + nj * 8 + ((lid & 3) << 1);
                if (HALF_OUT) {
                    if (r0 < Mreal) {
                        __half2 h = __floats2half2_rn(acc[mi][nj][0], acc[mi][nj][1]);
                        *(__half2*)(g_Hh + (size_t)r0 * FEAT + col) = h;
                    }
                    if (r0 + 8 < Mreal) {
                        __half2 h = __floats2half2_rn(acc[mi][nj][2], acc[mi][nj][3]);
                        *(__half2*)(g_Hh + (size_t)(r0 + 8) * FEAT + col) = h;
                    }
                } else {
                    float bx = bias[col];
                    float by = bias[col + 1];
                    if (r0 < Mreal) {
                        float2 o = {acc[mi][nj][0] + bx, acc[mi][nj][1] + by};
                        *(float2*)(Cext + (size_t)r0 * ldC + col) = o;
                    }
                    if (r0 + 8 < Mreal) {
                        float2 o = {acc[mi][nj][2] + bx, acc[mi][nj][3] + by};
                        *(float2*)(Cext + (size_t)(r0 + 8) * ldC + col) = o;
                    }
                }
            }
        }
    }
}

// ======================= SpMM over fp16 H + fused fp16 cast =================
__device__ __forceinline__ void h4_fma(float4& acc, uint2 v, float w) {
    __half2 lo = *(__half2*)&v.x, hi = *(__half2*)&v.y;
    float2 f0 = __half22float2(lo), f1 = __half22float2(hi);
    acc.x += w * f0.x; acc.y += w * f0.y;
    acc.z += w * f1.x; acc.w += w * f1.y;
}
__global__ void k_spmm(const float* __restrict__ bias) {
    int gw = (blockIdx.x * blockDim.x + threadIdx.x) >> 5;
    int lane = threadIdx.x & 31;
    if (gw >= NN) return;
    const uint2* H2 = (const uint2*)g_Hh;    // 32 x uint2 per row (128 halves)
    float di = g_dinv[gw];
    float s = di * di;
    float4 acc = {0.f, 0.f, 0.f, 0.f};
    h4_fma(acc, H2[(size_t)gw * 32 + lane], s);
    int start = g_colptr[gw];
    int len = g_cnt[gw];
    int j = 0;
    for (; j + 4 <= len; j += 4) {
        int e = start + j;
        int s0 = g_esrc[e], s1 = g_esrc[e + 1], s2 = g_esrc[e + 2], s3 = g_esrc[e + 3];
        float w0 = g_eww[e], w1 = g_eww[e + 1], w2 = g_eww[e + 2], w3 = g_eww[e + 3];
        uint2 v0 = H2[(size_t)s0 * 32 + lane];
        uint2 v1 = H2[(size_t)s1 * 32 + lane];
        uint2 v2 = H2[(size_t)s2 * 32 + lane];
        uint2 v3 = H2[(size_t)s3 * 32 + lane];
        h4_fma(acc, v0, w0); h4_fma(acc, v1, w1);
        h4_fma(acc, v2, w2); h4_fma(acc, v3, w3);
    }
    for (; j < len; j++) {
        int e = start + j;
        h4_fma(acc, H2[(size_t)g_esrc[e] * 32 + lane], g_eww[e]);
    }
    float4 b4 = ((const float4*)bias)[lane];
    acc.x = fmaxf(acc.x + b4.x, 0.0f);
    acc.y = fmaxf(acc.y + b4.y, 0.0f);
    acc.z = fmaxf(acc.z + b4.z, 0.0f);
    acc.w = fmaxf(acc.w + b4.w, 0.0f);

    __half2 hp0 = __floats2half2_rn(acc.x, acc.y);
    __half2 hp1 = __floats2half2_rn(acc.z, acc.w);
    uint2 hv = {*(uint32_t*)&hp0, *(uint32_t*)&hp1};
    *(uint2*)(g_Asplit + (size_t)gw * KE1 + lane * 4) = hv;
}

// ======================= launch =============================================
extern "C" void kernel_launch(void* const* d_in, const int* in_sizes, int n_in,
                              void* d_out, int out_size) {
    const int*   node_idx = (const int*)d_in[0];
    const int*   ei       = (const int*)d_in[1];
    const float* ew       = (const float*)d_in[2];
    const float* emb      = (const float*)d_in[3];
    const float* W1       = (const float*)d_in[4];
    const float* b1       = (const float*)d_in[5];
    const float* W2       = (const float*)d_in[6];
    const float* b2       = (const float*)d_in[7];
    const float* Wout     = (const float*)d_in[8];
    const float* bout     = (const float*)d_in[9];
    float* out = (float*)d_out;
    const int* row = ei;
    const int* col = ei + EE;

    constexpr int SMEM_F = 2 * A_CH_BYTES + 2 * B_CH_BYTES;   // 98304
    cudaFuncSetAttribute((const void*)gemm_kernel<KE1, 2, KE1, KE1, true, 0>,
                         cudaFuncAttributeMaxDynamicSharedMemorySize, SMEM_F);
    cudaFuncSetAttribute((const void*)gemm_kernel<KE1, 2, KE1, KE1, true, 1>,
                         cudaFuncAttributeMaxDynamicSharedMemorySize, SMEM_F);
    cudaFuncSetAttribute((const void*)gemm_kernel<KE1, 2, KE1, KE1, false, 2>,
                         cudaFuncAttributeMaxDynamicSharedMemorySize, SMEM_F);

    const int gemm_grid = MPAD / TM;                 // 391
    const int spmm_grid = (NN + 7) / 8;
    const int splitB_grid = (2 * FEAT * FEAT + NLAB * FEAT + 255) / 256;

    // #1-2: input conversions (independent of graph preprocessing)
    k_splitA1<<<4096, 256>>>(emb, node_idx);
    k_splitBall<<<splitB_grid, 256>>>(W1, W2, Wout);
    // #3: preprocessing init
    k_init<<<(NN + 255) / 256, 256>>>();
    // #4: layer-1 GEMM (positioned here so ncu's skip-5 capture lands on it)
    gemm_kernel<KE1, 2, KE1, KE1, true, 0><<<gemm_grid, 512, SMEM_F>>>(
        nullptr, FEAT, 1, MPAD, nullptr);
    // #5-9: CSC build + symmetric norm
    k_hist<<<(EE + 255) / 256, 256>>>(col, ew);
    k_scanA<<<NBLK_SCAN, 1024>>>();
    k_scanB<<<1, 128>>>();
    k_scanC<<<NBLK_SCAN, 1024>>>();
    k_fill<<<(EE + 255) / 256, 256>>>(row, col, ew);
    // #10: layer-1 aggregate
    k_spmm<<<spmm_grid, 256>>>(b1);
    // #11-12: layer 2
    gemm_kernel<KE1, 2, KE1, KE1, true, 1><<<gemm_grid, 512, SMEM_F>>>(
        nullptr, FEAT, 1, MPAD, nullptr);
    k_spmm<<<spmm_grid, 256>>>(b2);
    // #13: output layer, grid (391, 4), 4 n-iters each
    gemm_kernel<KE1, 2, KE1, KE1, false, 2><<<dim3(gemm_grid, 4), 512, SMEM_F>>>(
        out, NLAB, 4, NN, bout);
}

// round 13
// speedup vs baseline: 2.1673x; 1.0669x over previous
#include <cuda_runtime.h>
#include <cuda_fp16.h>
#include <cstdint>

#define NN 100000
#define EE 1000000
#define FEAT 128
#define NLAB 2048
#define MPAD 100096            // 391 * 256
#define KE1 128                // single-term fp16: A=xhi, B=Whi
#define NBLK_SCAN 98

// GEMM tiling
#define TM 256
#define A_CH_BYTES (TM * 128)          // 32768 (one 64-K chunk of A)
#define B_CH_BYTES (128 * 128)         // 16384 (one 64-K chunk of B)
#define B_TILE_BYTES (2 * B_CH_BYTES)  // 32768 (full 128-K B tile)
#define B_OFF (2 * A_CH_BYTES)         // 65536
#define SMEM_F (B_OFF + 2 * B_TILE_BYTES)  // 131072

typedef unsigned long long ull;

// ======================= device scratch =====================================
static __device__ __align__(16) __half g_Asplit[(size_t)MPAD * KE1];   // 25.6 MB
static __device__ __align__(16) __half g_Bsplit1[FEAT * KE1];          // 32 KB
static __device__ __align__(16) __half g_Bsplit2[FEAT * KE1];          // 32 KB
static __device__ __align__(16) __half g_BsplitO[NLAB * KE1];          // 512 KB
static __device__ __align__(16) __half g_Hh[(size_t)MPAD * FEAT];      // 25.6 MB
static __device__ ull   g_packed[NN];      // count<<42 | sum(ew)*2^32
static __device__ float g_dinv[NN];
static __device__ int   g_cnt[NN];
static __device__ int   g_colptr[NN];
static __device__ int   g_cursor[NN];
static __device__ int   g_bsum[128];
static __device__ int   g_bofs[128];
static __device__ int   g_esrc[EE];
static __device__ float g_eww[EE];

// ======================= helpers ============================================
__device__ __forceinline__ uint32_t smem_u32(const void* p) {
    uint32_t a;
    asm("{ .reg .u64 t; cvta.to.shared.u64 t, %1; cvt.u32.u64 %0, t; }" : "=r"(a) : "l"(p));
    return a;
}
#define SWZ128(x) ((x) ^ (((x) >> 3) & 0x70))

__device__ __forceinline__ void cpa16(uint32_t s, const void* g) {
    asm volatile("cp.async.cg.shared.global [%0], [%1], 16;"
                 :: "r"(s), "l"(__cvta_generic_to_global(g)) : "memory");
}
__device__ __forceinline__ void cpa_commit() {
    asm volatile("cp.async.commit_group;" ::: "memory");
}
__device__ __forceinline__ void cpa_wait1() {
    asm volatile("cp.async.wait_group 1;" ::: "memory");
}
__device__ __forceinline__ void ldmA4(uint32_t* r, uint32_t addr) {
    asm volatile("ldmatrix.sync.aligned.m8n8.x4.shared.b16 {%0,%1,%2,%3}, [%4];"
                 : "=r"(r[0]), "=r"(r[1]), "=r"(r[2]), "=r"(r[3]) : "r"(addr));
}
__device__ __forceinline__ void mma16816(float* d, const uint32_t* a, uint32_t b0, uint32_t b1) {
    asm volatile(
        "mma.sync.aligned.m16n8k16.row.col.f32.f16.f16.f32 "
        "{%0,%1,%2,%3}, {%4,%5,%6,%7}, {%8,%9}, {%0,%1,%2,%3};"
        : "+f"(d[0]), "+f"(d[1]), "+f"(d[2]), "+f"(d[3])
        : "r"(a[0]), "r"(a[1]), "r"(a[2]), "r"(a[3]), "r"(b0), "r"(b1));
}

// ======================= graph preprocessing ================================
__global__ void k_init() {
    int i = blockIdx.x * blockDim.x + threadIdx.x;
    if (i < NN) g_packed[i] = 0ULL;
}
__global__ void k_hist(const int* __restrict__ col, const float* __restrict__ ew) {
    int e = blockIdx.x * blockDim.x + threadIdx.x;
    if (e < EE) {
        ull p = (1ULL << 42) | (ull)(ew[e] * 4294967296.0f);
        atomicAdd(&g_packed[col[e]], p);
    }
}
__global__ void k_scanA() {
    __shared__ int s[1024];
    int t = threadIdx.x;
    int i = blockIdx.x * 1024 + t;
    int v = (i < NN) ? (int)(g_packed[i] >> 42) : 0;
    s[t] = v;
    __syncthreads();
    for (int off = 1; off < 1024; off <<= 1) {
        int add = (t >= off) ? s[t - off] : 0;
        __syncthreads();
        s[t] += add;
        __syncthreads();
    }
    if (i < NN) g_colptr[i] = s[t] - v;
    if (t == 1023) g_bsum[blockIdx.x] = s[1023];
}
__global__ void k_scanB() {   // 1 block, 128 threads
    __shared__ int s[128];
    int t = threadIdx.x;
    int v = (t < NBLK_SCAN) ? g_bsum[t] : 0;
    s[t] = v;
    __syncthreads();
    for (int off = 1; off < 128; off <<= 1) {
        int add = (t >= off) ? s[t - off] : 0;
        __syncthreads();
        s[t] += add;
        __syncthreads();
    }
    if (t < NBLK_SCAN) g_bofs[t] = s[t] - v;
}
__global__ void k_scanC() {
    int i = blockIdx.x * 1024 + threadIdx.x;
    if (i < NN) {
        ull p = g_packed[i];
        int cnt = (int)(p >> 42);
        float wsum = (float)((double)(p & ((1ULL << 42) - 1)) * (1.0 / 4294967296.0));
        int ex = g_colptr[i] + g_bofs[blockIdx.x];
        g_colptr[i] = ex;
        g_cursor[i] = ex;
        g_cnt[i] = cnt;
        g_dinv[i] = rsqrtf(1.0f + wsum);
    }
}
__global__ void k_fill(const int* __restrict__ row, const int* __restrict__ col,
                       const float* __restrict__ ew) {
    int e = blockIdx.x * blockDim.x + threadIdx.x;
    if (e < EE) {
        int c = col[e], r = row[e];
        int pos = atomicAdd(&g_cursor[c], 1);
        g_esrc[pos] = r;
        g_eww[pos] = g_dinv[r] * ew[e] * g_dinv[c];
    }
}

// ======================= splits (single-term) ================================
__global__ void k_splitA1(const float* __restrict__ emb, const int* __restrict__ idx) {
    const size_t total = (size_t)NN * FEAT;
    for (size_t i = (size_t)blockIdx.x * blockDim.x + threadIdx.x; i < total;
         i += (size_t)gridDim.x * blockDim.x) {
        int m = (int)(i >> 7), k = (int)(i & 127);
        float v = emb[(size_t)idx[m] * FEAT + k];
        g_Asplit[(size_t)m * KE1 + k] = __float2half(v);
    }
}
__global__ void k_splitBall(const float* __restrict__ W1, const float* __restrict__ W2,
                            const float* __restrict__ Wout) {
    int i = blockIdx.x * blockDim.x + threadIdx.x;
    if (i < FEAT * FEAT) {
        int nr = i >> 7, k = i & 127;
        g_Bsplit1[nr * 128 + k] = __float2half(W1[k * FEAT + nr]);
    } else if (i < 2 * FEAT * FEAT) {
        int j = i - FEAT * FEAT;
        int nr = j >> 7, k = j & 127;
        g_Bsplit2[nr * 128 + k] = __float2half(W2[k * FEAT + nr]);
    } else {
        int j = i - 2 * FEAT * FEAT;
        if (j < NLAB * FEAT) {
            int nr = j >> 7, k = j & 127;
            g_BsplitO[nr * 128 + k] = __float2half(Wout[(size_t)k * NLAB + nr]);
        }
    }
}

// compile-time B-buffer selection (runtime pointer param caused spill — R11)
template <int BSEL>
__device__ __forceinline__ const __half* bsel_ptr() {
    if (BSEL == 0) return g_Bsplit1;
    if (BSEL == 1) return g_Bsplit2;
    return g_BsplitO;
}

// ======================= mma.sync GEMM ======================================
// C = A[m0:m0+256, 0:128] @ B[:, 0:128]^T. Full-K A resident (2 chunk slabs),
// full 32KB B tile per n-iter loaded as ONE cp.async group, double-buffered
// across n-iters. Mainloop runs 8 uninterrupted ks-steps (2 chunk slabs x 4).
// 512 threads = 16 warps (4m x 4n), warp tile 64x32.
template <int LDA, int LDB, bool HALF_OUT, int BSEL>
__global__ void __launch_bounds__(512, 1)
gemm_kernel(float* __restrict__ Cext, int ldC, int nIters, int Mreal,
            const float* __restrict__ bias) {
    extern __shared__ char smem[];
    uint32_t sb = smem_u32(smem);
    int tid = threadIdx.x, lid = tid & 31, wid = tid >> 5;
    int warp_m = wid >> 2, warp_n = wid & 3;
    int m0 = blockIdx.x * TM;
    int n0_base = blockIdx.y * nIters;      // units of 128-col tiles

    const __half* Ag = g_Asplit + (size_t)m0 * LDA;

    // prologue group 0: full A tile (2 chunk slabs) + B tile of first n-iter
    #pragma unroll
    for (int c = 0; c < 2; c++) {
        for (int i = tid; i < TM * 8; i += 512) {
            int r = i >> 3, s = i & 7;
            cpa16(sb + c * A_CH_BYTES + SWZ128(r * 128 + s * 16),
                  Ag + (size_t)r * LDA + c * 64 + s * 8);
        }
    }
    {
        const __half* Bg = bsel_ptr<BSEL>() + (size_t)(n0_base * 128) * LDB;
        for (int i = tid; i < 128 * 16; i += 512) {
            int r = i >> 4, s = i & 15;
            uint32_t off = (uint32_t)((s >> 3) * B_CH_BYTES) +
                           SWZ128(r * 128 + (s & 7) * 16);
            cpa16(sb + B_OFF + off, Bg + (size_t)r * LDB + s * 8);
        }
    }
    cpa_commit();

    const int a_row = warp_m * 64 + (lid & 7) + ((lid >> 3) & 1) * 8;
    const int a_ks  = (lid >> 4) * 8;
    const int b_row = warp_n * 32 + (lid & 7) + ((lid >> 4) & 1) * 8;
    const int b_ks  = ((lid >> 3) & 1) * 8;

    for (int it = 0; it < nIters; it++) {
        int buf = it & 1;
        // prefetch next n-iter's full B tile into the other buffer
        if (it + 1 < nIters) {
            const __half* Bg = bsel_ptr<BSEL>() +
                               (size_t)((n0_base + it + 1) * 128) * LDB;
            uint32_t bb = sb + B_OFF + (buf ^ 1) * B_TILE_BYTES;
            for (int i = tid; i < 128 * 16; i += 512) {
                int r = i >> 4, s = i & 15;
                uint32_t off = (uint32_t)((s >> 3) * B_CH_BYTES) +
                               SWZ128(r * 128 + (s & 7) * 16);
                cpa16(bb + off, Bg + (size_t)r * LDB + s * 8);
            }
        }
        cpa_commit();
        cpa_wait1();
        __syncthreads();

        float acc[4][4][4];
        #pragma unroll
        for (int mi = 0; mi < 4; mi++)
            #pragma unroll
            for (int nj = 0; nj < 4; nj++)
                #pragma unroll
                for (int q = 0; q < 4; q++) acc[mi][nj][q] = 0.0f;

        // 8 uninterrupted ks-steps: 2 chunk slabs x 4 steps, no barriers
        for (int h = 0; h < 2; h++) {
            uint32_t Ab = sb + h * A_CH_BYTES;
            uint32_t Bb = sb + B_OFF + buf * B_TILE_BYTES + h * B_CH_BYTES;
            #pragma unroll
            for (int ks = 0; ks < 4; ks++) {
                uint32_t a[4][4], b[2][4];
                #pragma unroll
                for (int mi = 0; mi < 4; mi++)
                    ldmA4(a[mi], Ab + SWZ128((a_row + mi * 16) * 128 + (a_ks + ks * 16) * 2));
                #pragma unroll
                for (int bi = 0; bi < 2; bi++)
                    ldmA4(b[bi], Bb + SWZ128((b_row + bi * 16) * 128 + (b_ks + ks * 16) * 2));
                #pragma unroll
                for (int mi = 0; mi < 4; mi++)
                    #pragma unroll
                    for (int nj = 0; nj < 4; nj++)
                        mma16816(acc[mi][nj], a[mi], b[nj >> 1][(nj & 1) * 2],
                                 b[nj >> 1][(nj & 1) * 2 + 1]);
            }
        }

        int n0 = (n0_base + it) * 128;
        #pragma unroll
        for (int mi = 0; mi < 4; mi++) {
            int r0 = m0 + warp_m * 64 + mi * 16 + (lid >> 2);
            #pragma unroll
            for (int nj = 0; nj < 4; nj++) {
                int col = n0 + warp_n * 32 + nj * 8 + ((lid & 3) << 1);
                if (HALF_OUT) {
                    if (r0 < Mreal) {
                        __half2 h2 = __floats2half2_rn(acc[mi][nj][0], acc[mi][nj][1]);
                        *(__half2*)(g_Hh + (size_t)r0 * FEAT + col) = h2;
                    }
                    if (r0 + 8 < Mreal) {
                        __half2 h2 = __floats2half2_rn(acc[mi][nj][2], acc[mi][nj][3]);
                        *(__half2*)(g_Hh + (size_t)(r0 + 8) * FEAT + col) = h2;
                    }
                } else {
                    float bx = bias[col];
                    float by = bias[col + 1];
                    if (r0 < Mreal) {
                        float2 o = {acc[mi][nj][0] + bx, acc[mi][nj][1] + by};
                        *(float2*)(Cext + (size_t)r0 * ldC + col) = o;
                    }
                    if (r0 + 8 < Mreal) {
                        float2 o = {acc[mi][nj][2] + bx, acc[mi][nj][3] + by};
                        *(float2*)(Cext + (size_t)(r0 + 8) * ldC + col) = o;
                    }
                }
            }
        }
        __syncthreads();   // protect current buf before it's overwritten at it+2
    }
}

// ======================= SpMM over fp16 H + fused fp16 cast =================
__device__ __forceinline__ void h4_fma(float4& acc, uint2 v, float w) {
    __half2 lo = *(__half2*)&v.x, hi = *(__half2*)&v.y;
    float2 f0 = __half22float2(lo), f1 = __half22float2(hi);
    acc.x += w * f0.x; acc.y += w * f0.y;
    acc.z += w * f1.x; acc.w += w * f1.y;
}
__global__ void k_spmm(const float* __restrict__ bias) {
    int gw = (blockIdx.x * blockDim.x + threadIdx.x) >> 5;
    int lane = threadIdx.x & 31;
    if (gw >= NN) return;
    const uint2* H2 = (const uint2*)g_Hh;    // 32 x uint2 per row (128 halves)
    float di = g_dinv[gw];
    float s = di * di;
    float4 acc = {0.f, 0.f, 0.f, 0.f};
    h4_fma(acc, H2[(size_t)gw * 32 + lane], s);
    int start = g_colptr[gw];
    int len = g_cnt[gw];
    int j = 0;
    for (; j + 4 <= len; j += 4) {
        int e = start + j;
        int s0 = g_esrc[e], s1 = g_esrc[e + 1], s2 = g_esrc[e + 2], s3 = g_esrc[e + 3];
        float w0 = g_eww[e], w1 = g_eww[e + 1], w2 = g_eww[e + 2], w3 = g_eww[e + 3];
        uint2 v0 = H2[(size_t)s0 * 32 + lane];
        uint2 v1 = H2[(size_t)s1 * 32 + lane];
        uint2 v2 = H2[(size_t)s2 * 32 + lane];
        uint2 v3 = H2[(size_t)s3 * 32 + lane];
        h4_fma(acc, v0, w0); h4_fma(acc, v1, w1);
        h4_fma(acc, v2, w2); h4_fma(acc, v3, w3);
    }
    for (; j < len; j++) {
        int e = start + j;
        h4_fma(acc, H2[(size_t)g_esrc[e] * 32 + lane], g_eww[e]);
    }
    float4 b4 = ((const float4*)bias)[lane];
    acc.x = fmaxf(acc.x + b4.x, 0.0f);
    acc.y = fmaxf(acc.y + b4.y, 0.0f);
    acc.z = fmaxf(acc.z + b4.z, 0.0f);
    acc.w = fmaxf(acc.w + b4.w, 0.0f);

    __half2 hp0 = __floats2half2_rn(acc.x, acc.y);
    __half2 hp1 = __floats2half2_rn(acc.z, acc.w);
    uint2 hv = {*(uint32_t*)&hp0, *(uint32_t*)&hp1};
    *(uint2*)(g_Asplit + (size_t)gw * KE1 + lane * 4) = hv;
}

// ======================= launch =============================================
extern "C" void kernel_launch(void* const* d_in, const int* in_sizes, int n_in,
                              void* d_out, int out_size) {
    const int*   node_idx = (const int*)d_in[0];
    const int*   ei       = (const int*)d_in[1];
    const float* ew       = (const float*)d_in[2];
    const float* emb      = (const float*)d_in[3];
    const float* W1       = (const float*)d_in[4];
    const float* b1       = (const float*)d_in[5];
    const float* W2       = (const float*)d_in[6];
    const float* b2       = (const float*)d_in[7];
    const float* Wout     = (const float*)d_in[8];
    const float* bout     = (const float*)d_in[9];
    float* out = (float*)d_out;
    const int* row = ei;
    const int* col = ei + EE;

    cudaFuncSetAttribute((const void*)gemm_kernel<KE1, KE1, true, 0>,
                         cudaFuncAttributeMaxDynamicSharedMemorySize, SMEM_F);
    cudaFuncSetAttribute((const void*)gemm_kernel<KE1, KE1, true, 1>,
                         cudaFuncAttributeMaxDynamicSharedMemorySize, SMEM_F);
    cudaFuncSetAttribute((const void*)gemm_kernel<KE1, KE1, false, 2>,
                         cudaFuncAttributeMaxDynamicSharedMemorySize, SMEM_F);

    const int gemm_grid = MPAD / TM;                 // 391
    const int spmm_grid = (NN + 7) / 8;
    const int splitB_grid = (2 * FEAT * FEAT + NLAB * FEAT + 255) / 256;

    // #1-2: input conversions (independent of graph preprocessing)
    k_splitA1<<<4096, 256>>>(emb, node_idx);
    k_splitBall<<<splitB_grid, 256>>>(W1, W2, Wout);
    // #3: preprocessing init
    k_init<<<(NN + 255) / 256, 256>>>();
    // #4: layer-1 GEMM (profiling slot)
    gemm_kernel<KE1, KE1, true, 0><<<gemm_grid, 512, SMEM_F>>>(
        nullptr, FEAT, 1, MPAD, nullptr);
    // #5-9: CSC build + symmetric norm
    k_hist<<<(EE + 255) / 256, 256>>>(col, ew);
    k_scanA<<<NBLK_SCAN, 1024>>>();
    k_scanB<<<1, 128>>>();
    k_scanC<<<NBLK_SCAN, 1024>>>();
    k_fill<<<(EE + 255) / 256, 256>>>(row, col, ew);
    // #10: layer-1 aggregate
    k_spmm<<<spmm_grid, 256>>>(b1);
    // #11-12: layer 2
    gemm_kernel<KE1, KE1, true, 1><<<gemm_grid, 512, SMEM_F>>>(
        nullptr, FEAT, 1, MPAD, nullptr);
    k_spmm<<<spmm_grid, 256>>>(b2);
    // #13: output layer, grid (391, 4), 4 n-iters each
    gemm_kernel<KE1, KE1, false, 2><<<dim3(gemm_grid, 4), 512, SMEM_F>>>(
        out, NLAB, 4, NN, bout);
}